// round 3
// baseline (speedup 1.0000x reference)
#include <cuda_runtime.h>
#include <math.h>

#define NB 8
#define NC 3

// ---------------- scratch (device globals; no runtime allocation) ----------------
__device__ float g_x [NB*NC*256*256];   // sample conv output
__device__ float g_h0[NB*NC*512*512];   // ctx stage 0 out
__device__ float g_h1[NB*NC*256*256];   // ctx stage 1 out
__device__ float g_h2[NB*NC*128*128];   // ctx stage 2 out (pre-tanh feat_1)
__device__ float g_h3[NB*NC*64*64];     // ctx stage 3 out (pre-tanh feat_2)
__device__ float g_p1[NB*NC*128*128];
__device__ float g_p2[NB*NC*64*64];
__device__ float g_inv_sigma;
__device__ unsigned int g_counts[8];
__device__ unsigned int g_esti16;       // esti_size in units of 1/16 (exact integer)

// ---------------- init: zero accumulators + spectral norm of sample_w ----------------
__global__ void k_init(const float* __restrict__ w) {
    __shared__ double sG[9];
    int t = threadIdx.x;
    if (t < 8) g_counts[t] = 0u;
    if (t == 0) g_esti16 = 0u;
    if (t < 9) {
        int i = t / 3, j = t % 3;
        double s0 = 0.0, s1 = 0.0, s2 = 0.0, s3 = 0.0;
        #pragma unroll
        for (int k = 0; k < 48; k += 4) {
            s0 += (double)w[i*48 + k + 0] * (double)w[j*48 + k + 0];
            s1 += (double)w[i*48 + k + 1] * (double)w[j*48 + k + 1];
            s2 += (double)w[i*48 + k + 2] * (double)w[j*48 + k + 2];
            s3 += (double)w[i*48 + k + 3] * (double)w[j*48 + k + 3];
        }
        sG[t] = (s0 + s1) + (s2 + s3);
    }
    __syncthreads();
    if (t == 0) {
        double g00 = sG[0], g01 = sG[1], g02 = sG[2];
        double g11 = sG[4], g12 = sG[5], g22 = sG[8];
        double q  = (g00 + g11 + g22) / 3.0;
        double p1 = g01*g01 + g02*g02 + g12*g12;
        double d0 = g00 - q, d1 = g11 - q, d2 = g22 - q;
        double p2 = d0*d0 + d1*d1 + d2*d2 + 2.0*p1;
        double lam;
        if (p2 <= 1e-300) {
            lam = q;
        } else {
            double p = sqrt(p2 / 6.0);
            double ip = 1.0 / p;
            double b00 = d0*ip, b11 = d1*ip, b22 = d2*ip;
            double b01 = g01*ip, b02 = g02*ip, b12 = g12*ip;
            double detB = b00*(b11*b22 - b12*b12)
                        - b01*(b01*b22 - b12*b02)
                        + b02*(b01*b12 - b11*b02);
            double r = 0.5 * detB;
            r = fmin(1.0, fmax(-1.0, r));
            double phi = acos(r) / 3.0;
            lam = q + 2.0*p*cos(phi);
        }
        g_inv_sigma = (float)(1.0 / sqrt(lam));
    }
}

// ---------------- fused: sample conv (4x4 s4) + ctx stage 0 (3x3 s2 p1) ----------------
// One tile = 8 input rows (+1 top halo) of all 3 channels in smem, read once.
// Produces 2 sample output rows and 4 ctx0 output rows.
__global__ void k_fused(const float* __restrict__ x,
                        const float* __restrict__ samw,
                        const float* __restrict__ samb,
                        const float* __restrict__ cw,
                        const float* __restrict__ cb,
                        const float* __restrict__ bng,
                        const float* __restrict__ bnb) {
    extern __shared__ float sm[];          // [3][9][1024]
    __shared__ float ssw[144], ssb[3];
    __shared__ float scw[81], scb[3], sinv[3], sbb[3];

    int tid = threadIdx.x;
    if (tid < 144) ssw[tid] = samw[tid];
    if (tid >= 160 && tid < 241) scw[tid - 160] = cw[tid - 160];
    if (tid >= 256 && tid < 259) {
        int c = tid - 256;
        ssb[c]  = samb[c];
        scb[c]  = cb[c];
        sinv[c] = bng[c] / sqrtf(1.001f);
        sbb[c]  = bnb[c];
    }

    int tY = blockIdx.x;                   // tile index 0..127
    int b  = blockIdx.y;
    int gy0 = 8*tY - 1;

    // load 3 ch x 9 rows x 1024 floats as float4
    for (int idx = tid; idx < 3*9*256; idx += 512) {
        int ch  = idx / (9*256);
        int rem = idx - ch*(9*256);
        int r   = rem >> 8;
        int c4  = rem & 255;
        int gy  = gy0 + r;
        float4 v;
        if (gy >= 0) {
            v = *reinterpret_cast<const float4*>(
                    x + ((size_t)(b*3 + ch)*1024 + gy)*1024 + c4*4);
        } else {
            v = make_float4(0.f, 0.f, 0.f, 0.f);
        }
        *reinterpret_cast<float4*>(sm + (ch*9 + r)*1024 + c4*4) = v;
    }
    __syncthreads();

    // ---- sample part: 2 output rows x 256 cols (512 threads -> 1 each) ----
    {
        int srow = tid >> 8;               // 0..1
        int ox   = tid & 255;
        float a0 = 0.f, a1 = 0.f, a2 = 0.f;
        #pragma unroll
        for (int ic = 0; ic < 3; ic++) {
            #pragma unroll
            for (int ky = 0; ky < 4; ky++) {
                int r = 1 + 4*srow + ky;   // smem row (gy = 8t + 4*srow + ky)
                float4 v = reinterpret_cast<const float4*>(sm + (ic*9 + r)*1024)[ox];
                const float* w0 = &ssw[((0*3 + ic)*4 + ky)*4];
                const float* w1 = &ssw[((1*3 + ic)*4 + ky)*4];
                const float* w2 = &ssw[((2*3 + ic)*4 + ky)*4];
                a0 += w0[0]*v.x + w0[1]*v.y + w0[2]*v.z + w0[3]*v.w;
                a1 += w1[0]*v.x + w1[1]*v.y + w1[2]*v.z + w1[3]*v.w;
                a2 += w2[0]*v.x + w2[1]*v.y + w2[2]*v.z + w2[3]*v.w;
            }
        }
        float sg = g_inv_sigma;
        int oy = 2*tY + srow;
        g_x[((b*3 + 0)*256 + oy)*256 + ox] = a0*sg + ssb[0];
        g_x[((b*3 + 1)*256 + oy)*256 + ox] = a1*sg + ssb[1];
        g_x[((b*3 + 2)*256 + oy)*256 + ox] = a2*sg + ssb[2];
    }

    // ---- ctx0 part: 4 output rows x 512 cols ----
    int ox = tid;
    #pragma unroll
    for (int s = 0; s < 4; s++) {
        float a0 = scb[0], a1 = scb[1], a2 = scb[2];
        #pragma unroll
        for (int ic = 0; ic < 3; ic++) {
            float inv = sinv[ic], bb = sbb[ic];
            #pragma unroll
            for (int ky = 0; ky < 3; ky++) {
                bool rowok = (gy0 + 2*s + ky) >= 0;   // only false at tY=0,s=0,ky=0
                const float* rp = sm + (ic*9 + 2*s + ky)*1024 + 2*ox;
                #pragma unroll
                for (int kx = 0; kx < 3; kx++) {
                    int off = kx - 1;                  // ix = 2ox + kx - 1
                    bool colok = (ox > 0) || (kx > 0);
                    float raw = (rowok && colok) ? rp[off] : 0.f;
                    float v = (rowok && colok) ? fmaxf(fmaf(inv, raw, bb), 0.f) : 0.f;
                    int wi = ic*9 + ky*3 + kx;
                    a0 = fmaf(scw[wi],      v, a0);
                    a1 = fmaf(scw[27 + wi], v, a1);
                    a2 = fmaf(scw[54 + wi], v, a2);
                }
            }
        }
        int oy = 4*tY + s;
        g_h0[((b*3 + 0)*512 + oy)*512 + ox] = a0;
        g_h0[((b*3 + 1)*512 + oy)*512 + ox] = a1;
        g_h0[((b*3 + 2)*512 + oy)*512 + ox] = a2;
    }
}

// ---------------- smem-tiled ctx stage (stages 1..3): conv3x3(s2,p1) of relu(bn(in)) ----------------
template<int STAGE>
__global__ void k_ctx_t(const float* __restrict__ w,
                        const float* __restrict__ bias,
                        const float* __restrict__ bng,
                        const float* __restrict__ bnb) {
    constexpr int INH  = (STAGE == 1) ? 512 : (STAGE == 2) ? 256 : 128;
    constexpr int OUTW = INH / 2;
    constexpr int LOGW = (STAGE == 1) ? 8 : (STAGE == 2) ? 7 : 6;
    constexpr int R4   = INH / 4;
    const float* in = (STAGE == 1) ? g_h0 : (STAGE == 2) ? g_h1 : g_h2;
    float* outp     = (STAGE == 1) ? g_h1 : (STAGE == 2) ? g_h2 : g_h3;

    extern __shared__ float sm[];          // [3][9][INH], stores relu(bn(.))
    __shared__ float sw[81], sb[3];

    int tid = threadIdx.x;
    if (tid < 81) sw[tid] = w[tid];
    if (tid >= 96 && tid < 99) sb[tid - 96] = bias[tid - 96];

    int b = blockIdx.y;
    int gy0 = 8*(int)blockIdx.x - 1;
    float rsq = rsqrtf(1.001f);

    for (int idx = tid; idx < 3*9*R4; idx += 256) {
        int ch  = idx / (9*R4);
        int rem = idx - ch*(9*R4);
        int r   = rem / R4;
        int c4  = rem - r*R4;
        int gy  = gy0 + r;
        float4 v;
        if (gy >= 0) {
            v = *reinterpret_cast<const float4*>(
                    in + ((size_t)(b*3 + ch)*INH + gy)*INH + c4*4);
            float inv = __ldg(&bng[ch]) * rsq;
            float bb  = __ldg(&bnb[ch]);
            v.x = fmaxf(fmaf(inv, v.x, bb), 0.f);
            v.y = fmaxf(fmaf(inv, v.y, bb), 0.f);
            v.z = fmaxf(fmaf(inv, v.z, bb), 0.f);
            v.w = fmaxf(fmaf(inv, v.w, bb), 0.f);
        } else {
            v = make_float4(0.f, 0.f, 0.f, 0.f);  // zero-pad post-activation
        }
        *reinterpret_cast<float4*>(sm + (ch*9 + r)*INH + c4*4) = v;
    }
    __syncthreads();

    for (int p = tid; p < 4*OUTW; p += 256) {
        int ox = p & (OUTW - 1);
        int sY = p >> LOGW;
        float a0 = sb[0], a1 = sb[1], a2 = sb[2];
        #pragma unroll
        for (int ic = 0; ic < 3; ic++) {
            #pragma unroll
            for (int ky = 0; ky < 3; ky++) {
                const float* rp = sm + (ic*9 + 2*sY + ky)*INH + 2*ox;
                #pragma unroll
                for (int kx = 0; kx < 3; kx++) {
                    bool colok = (ox > 0) || (kx > 0);
                    float v = colok ? rp[kx - 1] : 0.f;
                    int wi = ic*9 + ky*3 + kx;
                    a0 = fmaf(sw[wi],      v, a0);
                    a1 = fmaf(sw[27 + wi], v, a1);
                    a2 = fmaf(sw[54 + wi], v, a2);
                }
            }
        }
        int oy = 4*blockIdx.x + sY;
        outp[((b*3 + 0)*(INH/2) + oy)*OUTW + ox] = a0;
        outp[((b*3 + 1)*(INH/2) + oy)*OUTW + ox] = a1;
        outp[((b*3 + 2)*(INH/2) + oy)*OUTW + ox] = a2;
    }
}

// ---------------- pool conv: 2x2 stride 2 pad 0 ----------------
template<int STAGE>
__global__ void k_pool(const float* __restrict__ w,
                       const float* __restrict__ bias) {
    const float* in;
    float* out;
    int inH;
    if (STAGE == 0) { in = g_x;  out = g_p1; inH = 256; }
    else            { in = g_p1; out = g_p2; inH = 128; }
    const int inW = inH, outH = inH >> 1, outW = inW >> 1;

    __shared__ float sw[36];
    __shared__ float sb[3];
    for (int j = threadIdx.x; j < 36; j += blockDim.x) sw[j] = w[j];
    if (threadIdx.x < 3) sb[threadIdx.x] = bias[threadIdx.x];
    __syncthreads();

    int ox = threadIdx.x;
    if (ox >= outW) return;
    int oy = blockIdx.x;
    int b  = blockIdx.y;

    float a0 = sb[0], a1 = sb[1], a2 = sb[2];
    #pragma unroll
    for (int ic = 0; ic < 3; ic++) {
        const float* base = in + ((size_t)(b*3 + ic)*inH + 2*oy)*inW + 2*ox;
        float2 r0 = *reinterpret_cast<const float2*>(base);
        float2 r1 = *reinterpret_cast<const float2*>(base + inW);
        const float* w0 = &sw[(0*3 + ic)*4];
        const float* w1 = &sw[(1*3 + ic)*4];
        const float* w2 = &sw[(2*3 + ic)*4];
        a0 += w0[0]*r0.x + w0[1]*r0.y + w0[2]*r1.x + w0[3]*r1.y;
        a1 += w1[0]*r0.x + w1[1]*r0.y + w1[2]*r1.x + w1[3]*r1.y;
        a2 += w2[0]*r0.x + w2[1]*r0.y + w2[2]*r1.x + w2[3]*r1.y;
    }
    out[((b*3 + 0)*outH + oy)*outW + ox] = a0;
    out[((b*3 + 1)*outH + oy)*outW + ox] = a1;
    out[((b*3 + 2)*outH + oy)*outW + ox] = a2;
}

// ---------------- main fused pass: conditions + soft VQ + stats ----------------
__global__ void k_main(const float* __restrict__ thresh,
                       const float* __restrict__ centers,
                       float* __restrict__ out) {
    __shared__ float sc[8];
    __shared__ unsigned int shist[8];
    __shared__ unsigned int sesti;
    __shared__ float sth[2];
    if (threadIdx.x < 8) { sc[threadIdx.x] = centers[threadIdx.x]; shist[threadIdx.x] = 0u; }
    if (threadIdx.x < 2) sth[threadIdx.x] = thresh[threadIdx.x];
    if (threadIdx.x == 0) sesti = 0u;
    __syncthreads();

    int i = blockIdx.x*blockDim.x + threadIdx.x;
    unsigned int ev = 0u;
    if (i < NB*NC*256*256) {
        int xp = i & 255, y = (i >> 8) & 255, bc = i >> 16;
        float xv = g_x[i];
        int hi = bc*16384 + (y >> 1)*128 + (xp >> 1);
        int qi = bc*4096  + (y >> 2)*64  + (xp >> 2);
        float f1 = 0.5f*(tanhf(g_h2[hi]) + 1.0f);
        float f2 = 0.5f*(tanhf(g_h3[qi]) + 1.0f);
        bool c2 = f2 < sth[1];
        bool c1 = (!c2) && (f1 < sth[0]);
        bool c0 = !(c1 || c2);
        float xq = xv;
        if (c1) xq = g_p1[hi];
        if (c2) xq = g_p2[qi];

        float dd[8];
        float dmin = 3.4e38f;
        int imin = 0;
        #pragma unroll
        for (int k = 0; k < 8; k++) {
            float t = xq - sc[k];
            dd[k] = t*t;
            if (dd[k] < dmin) { dmin = dd[k]; imin = k; }
        }
        float s = 0.f, sn = 0.f;
        #pragma unroll
        for (int k = 0; k < 8; k++) {
            float e = __expf(dmin - dd[k]);
            s += e;
            sn = fmaf(e, sc[k], sn);
        }
        out[i] = sn / s;

        ev = c0 ? 16u : (c1 ? 4u : 1u);
        if (c0) atomicAdd(&shist[imin], 1u);
    }
    unsigned int wsum = __reduce_add_sync(0xffffffffu, ev);
    if ((threadIdx.x & 31) == 0) atomicAdd(&sesti, wsum);
    __syncthreads();
    if (threadIdx.x < 8 && shist[threadIdx.x]) atomicAdd(&g_counts[threadIdx.x], shist[threadIdx.x]);
    if (threadIdx.x == 0) atomicAdd(&g_esti16, sesti);
}

// ---------------- mask_1 histogram (half res) ----------------
__global__ void k_mask1(const float* __restrict__ thresh,
                        const float* __restrict__ centers) {
    __shared__ float sc[8];
    __shared__ unsigned int shist[8];
    __shared__ float sth[2];
    if (threadIdx.x < 8) { sc[threadIdx.x] = centers[threadIdx.x]; shist[threadIdx.x] = 0u; }
    if (threadIdx.x < 2) sth[threadIdx.x] = thresh[threadIdx.x];
    __syncthreads();

    int i = blockIdx.x*blockDim.x + threadIdx.x;
    if (i < NB*NC*128*128) {
        int xp = i & 127, y = (i >> 7) & 127, bc = i >> 14;
        float f1 = 0.5f*(tanhf(g_h2[i]) + 1.0f);
        float f2 = 0.5f*(tanhf(g_h3[bc*4096 + (y >> 1)*64 + (xp >> 1)]) + 1.0f);
        if (f2 >= sth[1] && f1 < sth[0]) {
            float p = g_p1[i];
            float dmin = 3.4e38f; int imin = 0;
            #pragma unroll
            for (int k = 0; k < 8; k++) {
                float t = p - sc[k];
                float d = t*t;
                if (d < dmin) { dmin = d; imin = k; }
            }
            atomicAdd(&shist[imin], 1u);
        }
    }
    __syncthreads();
    if (threadIdx.x < 8 && shist[threadIdx.x]) atomicAdd(&g_counts[threadIdx.x], shist[threadIdx.x]);
}

// ---------------- mask_2 histogram (quarter res) ----------------
__global__ void k_mask2(const float* __restrict__ thresh,
                        const float* __restrict__ centers) {
    __shared__ float sc[8];
    __shared__ unsigned int shist[8];
    __shared__ float sth1;
    if (threadIdx.x < 8) { sc[threadIdx.x] = centers[threadIdx.x]; shist[threadIdx.x] = 0u; }
    if (threadIdx.x == 0) sth1 = thresh[1];
    __syncthreads();

    int i = blockIdx.x*blockDim.x + threadIdx.x;
    if (i < NB*NC*64*64) {
        float f2 = 0.5f*(tanhf(g_h3[i]) + 1.0f);
        if (f2 < sth1) {
            float p = g_p2[i];
            float dmin = 3.4e38f; int imin = 0;
            #pragma unroll
            for (int k = 0; k < 8; k++) {
                float t = p - sc[k];
                float d = t*t;
                if (d < dmin) { dmin = d; imin = k; }
            }
            atomicAdd(&shist[imin], 1u);
        }
    }
    __syncthreads();
    if (threadIdx.x < 8 && shist[threadIdx.x]) atomicAdd(&g_counts[threadIdx.x], shist[threadIdx.x]);
}

// ---------------- finalize scalars ----------------
__global__ void k_fin(float* __restrict__ out, int soft_n) {
    if (threadIdx.x == 0 && blockIdx.x == 0) {
        double tot = 0.0;
        for (int k = 0; k < 8; k++) tot += (double)g_counts[k];
        double c[8];
        double mean = 0.0;
        for (int k = 0; k < 8; k++) { c[k] = (double)g_counts[k] / tot; mean += c[k]; }
        mean /= 8.0;
        double var = 0.0;
        for (int k = 0; k < 8; k++) { double d = c[k] - mean; var += d*d; }
        double stdv = sqrt(var / 7.0);
        double esti = (double)g_esti16 / 16.0;
        double cr = (1.0/16.0) * esti / (256.0*256.0*3.0*8.0);
        out[soft_n]     = (float)cr;
        out[soft_n + 1] = (float)stdv;
    }
}

// ---------------- launch ----------------
extern "C" void kernel_launch(void* const* d_in, const int* in_sizes, int n_in,
                              void* d_out, int out_size) {
    const float* x_init   = (const float*)d_in[0];
    const float* thresh   = (const float*)d_in[1];
    const float* sample_w = (const float*)d_in[2];
    const float* sample_b = (const float*)d_in[3];
    const float* centers  = (const float*)d_in[4];
    const float* pool1_w  = (const float*)d_in[5];
    const float* pool1_b  = (const float*)d_in[6];
    const float* pool2_w  = (const float*)d_in[7];
    const float* pool2_b  = (const float*)d_in[8];
    const float* ctx_w    = (const float*)d_in[9];
    const float* ctx_b    = (const float*)d_in[10];
    const float* bng      = (const float*)d_in[11];
    const float* bnb      = (const float*)d_in[12];
    float* out = (float*)d_out;
    int soft_n = out_size - 2;

    const int SM_FUSED = 3*9*1024*4;   // 110592
    const int SM_C1    = 3*9*512*4;    // 55296
    const int SM_C2    = 3*9*256*4;    // 27648
    const int SM_C3    = 3*9*128*4;    // 13824
    cudaFuncSetAttribute(k_fused,    cudaFuncAttributeMaxDynamicSharedMemorySize, SM_FUSED);
    cudaFuncSetAttribute(k_ctx_t<1>, cudaFuncAttributeMaxDynamicSharedMemorySize, SM_C1);

    k_init<<<1, 32>>>(sample_w);
    k_fused<<<dim3(128, 8), 512, SM_FUSED>>>(x_init, sample_w, sample_b,
                                             ctx_w + 0*81, ctx_b + 0*3, bng + 0*3, bnb + 0*3);
    k_ctx_t<1><<<dim3(64, 8), 256, SM_C1>>>(ctx_w + 1*81, ctx_b + 1*3, bng + 1*3, bnb + 1*3);
    k_ctx_t<2><<<dim3(32, 8), 256, SM_C2>>>(ctx_w + 2*81, ctx_b + 2*3, bng + 2*3, bnb + 2*3);
    k_ctx_t<3><<<dim3(16, 8), 256, SM_C3>>>(ctx_w + 3*81, ctx_b + 3*3, bng + 3*3, bnb + 3*3);
    k_pool<0><<<dim3(128, 8), 128>>>(pool1_w, pool1_b);
    k_pool<1><<<dim3(64, 8),  64>>> (pool2_w, pool2_b);
    k_main<<<(NB*NC*256*256 + 255)/256, 256>>>(thresh, centers, out);
    k_mask1<<<(NB*NC*128*128 + 255)/256, 256>>>(thresh, centers);
    k_mask2<<<(NB*NC*64*64 + 255)/256, 256>>>(thresh, centers);
    k_fin<<<1, 32>>>(out, soft_n);
}

// round 4
// speedup vs baseline: 1.2570x; 1.2570x over previous
#include <cuda_runtime.h>
#include <math.h>

#define NB 8
#define NC 3

// ---------------- scratch (device globals; no runtime allocation) ----------------
__device__ float g_x [NB*NC*256*256];   // sample conv output
__device__ float g_h0[NB*NC*512*512];   // ctx stage 0 out
__device__ float g_h1[NB*NC*256*256];   // ctx stage 1 out
__device__ float g_h2[NB*NC*128*128];   // ctx stage 2 out (pre-tanh feat_1)
__device__ float g_h3[NB*NC*64*64];     // ctx stage 3 out (pre-tanh feat_2)
__device__ float g_p1[NB*NC*128*128];
__device__ float g_p2[NB*NC*64*64];
__device__ float g_inv_sigma;
__device__ unsigned int g_counts[8];
__device__ unsigned int g_esti16;       // esti_size in units of 1/16 (exact integer)

// ---------------- init: zero accumulators + spectral norm of sample_w ----------------
__global__ void k_init(const float* __restrict__ w) {
    __shared__ double sG[9];
    int t = threadIdx.x;
    if (t < 8) g_counts[t] = 0u;
    if (t == 0) g_esti16 = 0u;
    if (t < 9) {
        int i = t / 3, j = t % 3;
        double s0 = 0.0, s1 = 0.0, s2 = 0.0, s3 = 0.0;
        #pragma unroll
        for (int k = 0; k < 48; k += 4) {
            s0 += (double)w[i*48 + k + 0] * (double)w[j*48 + k + 0];
            s1 += (double)w[i*48 + k + 1] * (double)w[j*48 + k + 1];
            s2 += (double)w[i*48 + k + 2] * (double)w[j*48 + k + 2];
            s3 += (double)w[i*48 + k + 3] * (double)w[j*48 + k + 3];
        }
        sG[t] = (s0 + s1) + (s2 + s3);
    }
    __syncthreads();
    if (t == 0) {
        double g00 = sG[0], g01 = sG[1], g02 = sG[2];
        double g11 = sG[4], g12 = sG[5], g22 = sG[8];
        double q  = (g00 + g11 + g22) / 3.0;
        double p1 = g01*g01 + g02*g02 + g12*g12;
        double d0 = g00 - q, d1 = g11 - q, d2 = g22 - q;
        double p2 = d0*d0 + d1*d1 + d2*d2 + 2.0*p1;
        double lam;
        if (p2 <= 1e-300) {
            lam = q;
        } else {
            double p = sqrt(p2 / 6.0);
            double ip = 1.0 / p;
            double b00 = d0*ip, b11 = d1*ip, b22 = d2*ip;
            double b01 = g01*ip, b02 = g02*ip, b12 = g12*ip;
            double detB = b00*(b11*b22 - b12*b12)
                        - b01*(b01*b22 - b12*b02)
                        + b02*(b01*b12 - b11*b02);
            double r = 0.5 * detB;
            r = fmin(1.0, fmax(-1.0, r));
            double phi = acos(r) / 3.0;
            lam = q + 2.0*p*cos(phi);
        }
        g_inv_sigma = (float)(1.0 / sqrt(lam));
    }
}

// ---------------- sample conv: 4x4, stride 4, pad 0; 1024 -> 256 ----------------
__global__ void k_sample(const float* __restrict__ x,
                         const float* __restrict__ w,
                         const float* __restrict__ bias) {
    __shared__ float sw[144];
    __shared__ float sb[3];
    __shared__ float sinv;
    for (int j = threadIdx.x; j < 144; j += 256) sw[j] = w[j];
    if (threadIdx.x < 3) sb[threadIdx.x] = bias[threadIdx.x];
    if (threadIdx.x == 0) sinv = g_inv_sigma;
    __syncthreads();

    int ox = threadIdx.x;      // 0..255
    int oy = blockIdx.x;       // 0..255
    int b  = blockIdx.y;       // 0..7
    float a0 = 0.f, a1 = 0.f, a2 = 0.f;
    #pragma unroll
    for (int ic = 0; ic < 3; ic++) {
        const float* base = x + (((b*3 + ic)*1024) + oy*4)*1024 + ox*4;
        #pragma unroll
        for (int ky = 0; ky < 4; ky++) {
            float4 v = *reinterpret_cast<const float4*>(base + ky*1024);
            const float* w0 = &sw[((0*3 + ic)*4 + ky)*4];
            const float* w1 = &sw[((1*3 + ic)*4 + ky)*4];
            const float* w2 = &sw[((2*3 + ic)*4 + ky)*4];
            a0 += w0[0]*v.x + w0[1]*v.y + w0[2]*v.z + w0[3]*v.w;
            a1 += w1[0]*v.x + w1[1]*v.y + w1[2]*v.z + w1[3]*v.w;
            a2 += w2[0]*v.x + w2[1]*v.y + w2[2]*v.z + w2[3]*v.w;
        }
    }
    g_x[((b*3 + 0)*256 + oy)*256 + ox] = a0*sinv + sb[0];
    g_x[((b*3 + 1)*256 + oy)*256 + ox] = a1*sinv + sb[1];
    g_x[((b*3 + 2)*256 + oy)*256 + ox] = a2*sinv + sb[2];
}

// ---------------- ctx conv stage: conv3x3(s2,p1) of relu(bn(in)), 2 outputs/thread ----------------
// Thread j computes ox = 2j and 2j+1. Needed input cols 4j-1..4j+3 come from
// one aligned float4 + one guarded scalar. BN+ReLU applied once per value.
template<int STAGE>
__global__ void k_ctx(const float* __restrict__ xin,
                      const float* __restrict__ w,
                      const float* __restrict__ bias,
                      const float* __restrict__ bng,
                      const float* __restrict__ bnb) {
    constexpr int INH  = (STAGE == 0) ? 1024 : (STAGE == 1) ? 512 : (STAGE == 2) ? 256 : 128;
    constexpr int OUTW = INH / 2;
    constexpr int JW   = OUTW / 2;         // thread-pairs per output row
    const float* in = (STAGE == 0) ? xin : (STAGE == 1) ? g_h0 : (STAGE == 2) ? g_h1 : g_h2;
    float* outp     = (STAGE == 0) ? g_h0 : (STAGE == 1) ? g_h1 : (STAGE == 2) ? g_h2 : g_h3;

    __shared__ float sw[81];
    __shared__ float sb[3], sinv[3], sbb[3];
    for (int t = threadIdx.x; t < 81; t += blockDim.x) sw[t] = w[t];
    if (threadIdx.x < 3) {
        sb[threadIdx.x]   = bias[threadIdx.x];
        sinv[threadIdx.x] = bng[threadIdx.x] * rsqrtf(1.001f);
        sbb[threadIdx.x]  = bnb[threadIdx.x];
    }
    __syncthreads();

    int p  = blockIdx.x*blockDim.x + threadIdx.x;
    int j  = p & (JW - 1);
    int oy = p >> ((STAGE == 0) ? 8 : (STAGE == 1) ? 7 : (STAGE == 2) ? 6 : 5);
    int b  = blockIdx.y;

    float a00 = sb[0], a01 = sb[0];
    float a10 = sb[1], a11 = sb[1];
    float a20 = sb[2], a21 = sb[2];

    #pragma unroll
    for (int ic = 0; ic < 3; ic++) {
        const float* base = in + (size_t)(b*3 + ic)*INH*INH;
        float inv = sinv[ic], bb = sbb[ic];
        #pragma unroll
        for (int ky = 0; ky < 3; ky++) {
            int iy = 2*oy + ky - 1;
            if ((unsigned)iy >= (unsigned)INH) continue;
            const float* rowp = base + (size_t)iy*INH + 4*j;
            float4 v4 = *reinterpret_cast<const float4*>(rowp);
            float u0 = 0.f;
            if (j > 0) {
                float vm = rowp[-1];
                u0 = fmaxf(fmaf(inv, vm, bb), 0.f);
            }
            float u1 = fmaxf(fmaf(inv, v4.x, bb), 0.f);
            float u2 = fmaxf(fmaf(inv, v4.y, bb), 0.f);
            float u3 = fmaxf(fmaf(inv, v4.z, bb), 0.f);
            float u4 = fmaxf(fmaf(inv, v4.w, bb), 0.f);
            const float* wp = &sw[ic*9 + ky*3];
            // ox=2j   : ix = 4j-1, 4j, 4j+1 -> u0,u1,u2
            // ox=2j+1 : ix = 4j+1, 4j+2, 4j+3 -> u2,u3,u4
            a00 = fmaf(wp[0], u0, fmaf(wp[1], u1, fmaf(wp[2], u2, a00)));
            a01 = fmaf(wp[0], u2, fmaf(wp[1], u3, fmaf(wp[2], u4, a01)));
            a10 = fmaf(wp[27], u0, fmaf(wp[28], u1, fmaf(wp[29], u2, a10)));
            a11 = fmaf(wp[27], u2, fmaf(wp[28], u3, fmaf(wp[29], u4, a11)));
            a20 = fmaf(wp[54], u0, fmaf(wp[55], u1, fmaf(wp[56], u2, a20)));
            a21 = fmaf(wp[54], u2, fmaf(wp[55], u3, fmaf(wp[56], u4, a21)));
        }
    }
    size_t o0 = ((size_t)(b*3 + 0)*OUTW + oy)*OUTW + 2*j;
    size_t o1 = ((size_t)(b*3 + 1)*OUTW + oy)*OUTW + 2*j;
    size_t o2 = ((size_t)(b*3 + 2)*OUTW + oy)*OUTW + 2*j;
    *reinterpret_cast<float2*>(outp + o0) = make_float2(a00, a01);
    *reinterpret_cast<float2*>(outp + o1) = make_float2(a10, a11);
    *reinterpret_cast<float2*>(outp + o2) = make_float2(a20, a21);
}

// ---------------- pool conv: 2x2 stride 2 pad 0 ----------------
template<int STAGE>
__global__ void k_pool(const float* __restrict__ w,
                       const float* __restrict__ bias) {
    const float* in;
    float* out;
    int inH;
    if (STAGE == 0) { in = g_x;  out = g_p1; inH = 256; }
    else            { in = g_p1; out = g_p2; inH = 128; }
    const int inW = inH, outH = inH >> 1, outW = inW >> 1;

    __shared__ float sw[36];
    __shared__ float sb[3];
    for (int j = threadIdx.x; j < 36; j += blockDim.x) sw[j] = w[j];
    if (threadIdx.x < 3) sb[threadIdx.x] = bias[threadIdx.x];
    __syncthreads();

    int ox = threadIdx.x;
    if (ox >= outW) return;
    int oy = blockIdx.x;
    int b  = blockIdx.y;

    float a0 = sb[0], a1 = sb[1], a2 = sb[2];
    #pragma unroll
    for (int ic = 0; ic < 3; ic++) {
        const float* base = in + ((size_t)(b*3 + ic)*inH + 2*oy)*inW + 2*ox;
        float2 r0 = *reinterpret_cast<const float2*>(base);
        float2 r1 = *reinterpret_cast<const float2*>(base + inW);
        const float* w0 = &sw[(0*3 + ic)*4];
        const float* w1 = &sw[(1*3 + ic)*4];
        const float* w2 = &sw[(2*3 + ic)*4];
        a0 += w0[0]*r0.x + w0[1]*r0.y + w0[2]*r1.x + w0[3]*r1.y;
        a1 += w1[0]*r0.x + w1[1]*r0.y + w1[2]*r1.x + w1[3]*r1.y;
        a2 += w2[0]*r0.x + w2[1]*r0.y + w2[2]*r1.x + w2[3]*r1.y;
    }
    out[((b*3 + 0)*outH + oy)*outW + ox] = a0;
    out[((b*3 + 1)*outH + oy)*outW + ox] = a1;
    out[((b*3 + 2)*outH + oy)*outW + ox] = a2;
}

// ---------------- main fused pass: conditions + soft VQ + stats ----------------
__global__ void k_main(const float* __restrict__ thresh,
                       const float* __restrict__ centers,
                       float* __restrict__ out) {
    __shared__ float sc[8];
    __shared__ unsigned int shist[8];
    __shared__ unsigned int sesti;
    __shared__ float sth[2];
    if (threadIdx.x < 8) { sc[threadIdx.x] = centers[threadIdx.x]; shist[threadIdx.x] = 0u; }
    if (threadIdx.x < 2) sth[threadIdx.x] = thresh[threadIdx.x];
    if (threadIdx.x == 0) sesti = 0u;
    __syncthreads();

    int i = blockIdx.x*blockDim.x + threadIdx.x;
    unsigned int ev = 0u;
    if (i < NB*NC*256*256) {
        int xp = i & 255, y = (i >> 8) & 255, bc = i >> 16;
        float xv = g_x[i];
        int hi = bc*16384 + (y >> 1)*128 + (xp >> 1);
        int qi = bc*4096  + (y >> 2)*64  + (xp >> 2);
        float f1 = 0.5f*(tanhf(g_h2[hi]) + 1.0f);
        float f2 = 0.5f*(tanhf(g_h3[qi]) + 1.0f);
        bool c2 = f2 < sth[1];
        bool c1 = (!c2) && (f1 < sth[0]);
        bool c0 = !(c1 || c2);
        float xq = xv;
        if (c1) xq = g_p1[hi];
        if (c2) xq = g_p2[qi];

        float dd[8];
        float dmin = 3.4e38f;
        int imin = 0;
        #pragma unroll
        for (int k = 0; k < 8; k++) {
            float t = xq - sc[k];
            dd[k] = t*t;
            if (dd[k] < dmin) { dmin = dd[k]; imin = k; }
        }
        float s = 0.f, sn = 0.f;
        #pragma unroll
        for (int k = 0; k < 8; k++) {
            float e = __expf(dmin - dd[k]);
            s += e;
            sn = fmaf(e, sc[k], sn);
        }
        out[i] = sn / s;

        ev = c0 ? 16u : (c1 ? 4u : 1u);
        if (c0) atomicAdd(&shist[imin], 1u);
    }
    unsigned int wsum = __reduce_add_sync(0xffffffffu, ev);
    if ((threadIdx.x & 31) == 0) atomicAdd(&sesti, wsum);
    __syncthreads();
    if (threadIdx.x < 8 && shist[threadIdx.x]) atomicAdd(&g_counts[threadIdx.x], shist[threadIdx.x]);
    if (threadIdx.x == 0) atomicAdd(&g_esti16, sesti);
}

// ---------------- mask_1 histogram (half res) ----------------
__global__ void k_mask1(const float* __restrict__ thresh,
                        const float* __restrict__ centers) {
    __shared__ float sc[8];
    __shared__ unsigned int shist[8];
    __shared__ float sth[2];
    if (threadIdx.x < 8) { sc[threadIdx.x] = centers[threadIdx.x]; shist[threadIdx.x] = 0u; }
    if (threadIdx.x < 2) sth[threadIdx.x] = thresh[threadIdx.x];
    __syncthreads();

    int i = blockIdx.x*blockDim.x + threadIdx.x;
    if (i < NB*NC*128*128) {
        int xp = i & 127, y = (i >> 7) & 127, bc = i >> 14;
        float f1 = 0.5f*(tanhf(g_h2[i]) + 1.0f);
        float f2 = 0.5f*(tanhf(g_h3[bc*4096 + (y >> 1)*64 + (xp >> 1)]) + 1.0f);
        if (f2 >= sth[1] && f1 < sth[0]) {
            float p = g_p1[i];
            float dmin = 3.4e38f; int imin = 0;
            #pragma unroll
            for (int k = 0; k < 8; k++) {
                float t = p - sc[k];
                float d = t*t;
                if (d < dmin) { dmin = d; imin = k; }
            }
            atomicAdd(&shist[imin], 1u);
        }
    }
    __syncthreads();
    if (threadIdx.x < 8 && shist[threadIdx.x]) atomicAdd(&g_counts[threadIdx.x], shist[threadIdx.x]);
}

// ---------------- mask_2 histogram (quarter res) ----------------
__global__ void k_mask2(const float* __restrict__ thresh,
                        const float* __restrict__ centers) {
    __shared__ float sc[8];
    __shared__ unsigned int shist[8];
    __shared__ float sth1;
    if (threadIdx.x < 8) { sc[threadIdx.x] = centers[threadIdx.x]; shist[threadIdx.x] = 0u; }
    if (threadIdx.x == 0) sth1 = thresh[1];
    __syncthreads();

    int i = blockIdx.x*blockDim.x + threadIdx.x;
    if (i < NB*NC*64*64) {
        float f2 = 0.5f*(tanhf(g_h3[i]) + 1.0f);
        if (f2 < sth1) {
            float p = g_p2[i];
            float dmin = 3.4e38f; int imin = 0;
            #pragma unroll
            for (int k = 0; k < 8; k++) {
                float t = p - sc[k];
                float d = t*t;
                if (d < dmin) { dmin = d; imin = k; }
            }
            atomicAdd(&shist[imin], 1u);
        }
    }
    __syncthreads();
    if (threadIdx.x < 8 && shist[threadIdx.x]) atomicAdd(&g_counts[threadIdx.x], shist[threadIdx.x]);
}

// ---------------- finalize scalars ----------------
__global__ void k_fin(float* __restrict__ out, int soft_n) {
    if (threadIdx.x == 0 && blockIdx.x == 0) {
        double tot = 0.0;
        for (int k = 0; k < 8; k++) tot += (double)g_counts[k];
        double c[8];
        double mean = 0.0;
        for (int k = 0; k < 8; k++) { c[k] = (double)g_counts[k] / tot; mean += c[k]; }
        mean /= 8.0;
        double var = 0.0;
        for (int k = 0; k < 8; k++) { double d = c[k] - mean; var += d*d; }
        double stdv = sqrt(var / 7.0);
        double esti = (double)g_esti16 / 16.0;
        double cr = (1.0/16.0) * esti / (256.0*256.0*3.0*8.0);
        out[soft_n]     = (float)cr;
        out[soft_n + 1] = (float)stdv;
    }
}

// ---------------- launch ----------------
extern "C" void kernel_launch(void* const* d_in, const int* in_sizes, int n_in,
                              void* d_out, int out_size) {
    const float* x_init   = (const float*)d_in[0];
    const float* thresh   = (const float*)d_in[1];
    const float* sample_w = (const float*)d_in[2];
    const float* sample_b = (const float*)d_in[3];
    const float* centers  = (const float*)d_in[4];
    const float* pool1_w  = (const float*)d_in[5];
    const float* pool1_b  = (const float*)d_in[6];
    const float* pool2_w  = (const float*)d_in[7];
    const float* pool2_b  = (const float*)d_in[8];
    const float* ctx_w    = (const float*)d_in[9];
    const float* ctx_b    = (const float*)d_in[10];
    const float* bng      = (const float*)d_in[11];
    const float* bnb      = (const float*)d_in[12];
    float* out = (float*)d_out;
    int soft_n = out_size - 2;

    k_init<<<1, 32>>>(sample_w);
    k_sample<<<dim3(256, 8), 256>>>(x_init, sample_w, sample_b);
    // grid: (JW*OUTH)/256 blocks; JW=OUTW/2
    k_ctx<0><<<dim3(512, 8), 256>>>(x_init, ctx_w + 0*81, ctx_b + 0*3, bng + 0*3, bnb + 0*3);
    k_ctx<1><<<dim3(128, 8), 256>>>(x_init, ctx_w + 1*81, ctx_b + 1*3, bng + 1*3, bnb + 1*3);
    k_ctx<2><<<dim3(32, 8),  256>>>(x_init, ctx_w + 2*81, ctx_b + 2*3, bng + 2*3, bnb + 2*3);
    k_ctx<3><<<dim3(8, 8),   256>>>(x_init, ctx_w + 3*81, ctx_b + 3*3, bng + 3*3, bnb + 3*3);
    k_pool<0><<<dim3(128, 8), 128>>>(pool1_w, pool1_b);
    k_pool<1><<<dim3(64, 8),  64>>> (pool2_w, pool2_b);
    k_main<<<(NB*NC*256*256 + 255)/256, 256>>>(thresh, centers, out);
    k_mask1<<<(NB*NC*128*128 + 255)/256, 256>>>(thresh, centers);
    k_mask2<<<(NB*NC*64*64 + 255)/256, 256>>>(thresh, centers);
    k_fin<<<1, 32>>>(out, soft_n);
}

// round 5
// speedup vs baseline: 1.4924x; 1.1872x over previous
#include <cuda_runtime.h>
#include <math.h>

#define NB 8
#define NC 3

// ---------------- scratch (device globals; no runtime allocation) ----------------
__device__ float g_x [NB*NC*256*256];   // sample conv output
__device__ float g_h0[NB*NC*512*512];   // ctx stage 0 out
__device__ float g_h1[NB*NC*256*256];   // ctx stage 1 out
__device__ float g_h2[NB*NC*128*128];   // ctx stage 2 out (pre-tanh feat_1)
__device__ float g_h3[NB*NC*64*64];     // ctx stage 3 out (pre-tanh feat_2)
__device__ float g_p1[NB*NC*128*128];
__device__ float g_p2[NB*NC*64*64];
__device__ float g_inv_sigma;
__device__ unsigned int g_counts[8];
__device__ unsigned int g_esti16;       // esti_size in units of 1/16 (exact integer)

// ---------------- init: zero accumulators + spectral norm of sample_w ----------------
__global__ void k_init(const float* __restrict__ w) {
    __shared__ double sG[9];
    int t = threadIdx.x;
    if (t < 8) g_counts[t] = 0u;
    if (t == 0) g_esti16 = 0u;
    if (t < 9) {
        int i = t / 3, j = t % 3;
        double s0 = 0.0, s1 = 0.0, s2 = 0.0, s3 = 0.0;
        #pragma unroll
        for (int k = 0; k < 48; k += 4) {
            s0 += (double)w[i*48 + k + 0] * (double)w[j*48 + k + 0];
            s1 += (double)w[i*48 + k + 1] * (double)w[j*48 + k + 1];
            s2 += (double)w[i*48 + k + 2] * (double)w[j*48 + k + 2];
            s3 += (double)w[i*48 + k + 3] * (double)w[j*48 + k + 3];
        }
        sG[t] = (s0 + s1) + (s2 + s3);
    }
    __syncthreads();
    if (t == 0) {
        double g00 = sG[0], g01 = sG[1], g02 = sG[2];
        double g11 = sG[4], g12 = sG[5], g22 = sG[8];
        double q  = (g00 + g11 + g22) / 3.0;
        double p1 = g01*g01 + g02*g02 + g12*g12;
        double d0 = g00 - q, d1 = g11 - q, d2 = g22 - q;
        double p2 = d0*d0 + d1*d1 + d2*d2 + 2.0*p1;
        double lam;
        if (p2 <= 1e-300) {
            lam = q;
        } else {
            double p = sqrt(p2 / 6.0);
            double ip = 1.0 / p;
            double b00 = d0*ip, b11 = d1*ip, b22 = d2*ip;
            double b01 = g01*ip, b02 = g02*ip, b12 = g12*ip;
            double detB = b00*(b11*b22 - b12*b12)
                        - b01*(b01*b22 - b12*b02)
                        + b02*(b01*b12 - b11*b02);
            double r = 0.5 * detB;
            r = fmin(1.0, fmax(-1.0, r));
            double phi = acos(r) / 3.0;
            lam = q + 2.0*p*cos(phi);
        }
        g_inv_sigma = (float)(1.0 / sqrt(lam));
    }
}

// ---------------- fused: sample conv (4x4 s4) + ctx stage 0 (3x3 s2 p1) ----------------
// Thread (oy, ox) reads a 5x5 patch (rows 4oy-1..4oy+3, cols 4ox-1..4ox+3) per
// channel and emits 1 sample pixel (3ch) + a 2x2 ctx0 block (3ch). x_init is
// read exactly once (plus small halo). No smem data tiles, no syncs.
__global__ void k_fused(const float* __restrict__ x,
                        const float* __restrict__ samw,
                        const float* __restrict__ samb,
                        const float* __restrict__ cw,
                        const float* __restrict__ cb,
                        const float* __restrict__ bng,
                        const float* __restrict__ bnb) {
    __shared__ float ssw[144], ssb[3];
    __shared__ float scw[81], scb[3], sinv[3], sbb[3];
    int tid = threadIdx.x;
    if (tid < 144) ssw[tid] = samw[tid];
    if (tid < 81)  scw[tid] = cw[tid];
    if (tid < 3) {
        ssb[tid]  = samb[tid];
        scb[tid]  = cb[tid];
        sinv[tid] = bng[tid] * rsqrtf(1.001f);
        sbb[tid]  = bnb[tid];
    }
    __syncthreads();

    int ox = threadIdx.x;      // 0..255
    int oy = blockIdx.x;       // 0..255
    int b  = blockIdx.y;

    float as0 = 0.f, as1 = 0.f, as2 = 0.f;      // sample accumulators
    float ac[2][2][3];                           // [sy][sx][oc]
    #pragma unroll
    for (int sy = 0; sy < 2; sy++)
        #pragma unroll
        for (int sx = 0; sx < 2; sx++)
            #pragma unroll
            for (int oc = 0; oc < 3; oc++)
                ac[sy][sx][oc] = scb[oc];

    bool left = (ox > 0);

    #pragma unroll
    for (int ic = 0; ic < 3; ic++) {
        const float* base = x + (size_t)(b*3 + ic)*1024*1024;
        float inv = sinv[ic], bb = sbb[ic];
        #pragma unroll
        for (int r5 = 0; r5 < 5; r5++) {
            int iy = 4*oy + r5 - 1;
            float u0, u1, u2, u3, u4;
            if (iy >= 0) {
                const float* rp = base + (size_t)iy*1024 + 4*ox;
                float4 v4 = *reinterpret_cast<const float4*>(rp);
                float vm = left ? rp[-1] : 0.f;
                u0 = left ? fmaxf(fmaf(inv, vm, bb), 0.f) : 0.f;
                u1 = fmaxf(fmaf(inv, v4.x, bb), 0.f);
                u2 = fmaxf(fmaf(inv, v4.y, bb), 0.f);
                u3 = fmaxf(fmaf(inv, v4.z, bb), 0.f);
                u4 = fmaxf(fmaf(inv, v4.w, bb), 0.f);
                if (r5 >= 1) {                    // sample uses rows 4oy..4oy+3
                    int ky = r5 - 1;
                    const float* w0 = &ssw[(0*3 + ic)*16 + ky*4];
                    const float* w1 = &ssw[(1*3 + ic)*16 + ky*4];
                    const float* w2 = &ssw[(2*3 + ic)*16 + ky*4];
                    as0 += w0[0]*v4.x + w0[1]*v4.y + w0[2]*v4.z + w0[3]*v4.w;
                    as1 += w1[0]*v4.x + w1[1]*v4.y + w1[2]*v4.z + w1[3]*v4.w;
                    as2 += w2[0]*v4.x + w2[1]*v4.y + w2[2]*v4.z + w2[3]*v4.w;
                }
            } else {
                u0 = u1 = u2 = u3 = u4 = 0.f;
            }
            // ctx0: local row r5 is tap ky=r5 for sy=0 (r5<=2), ky=r5-2 for sy=1 (r5>=2)
            if (r5 <= 2) {
                #pragma unroll
                for (int oc = 0; oc < 3; oc++) {
                    const float* wp = &scw[oc*27 + ic*9 + r5*3];
                    ac[0][0][oc] = fmaf(wp[0], u0, fmaf(wp[1], u1, fmaf(wp[2], u2, ac[0][0][oc])));
                    ac[0][1][oc] = fmaf(wp[0], u2, fmaf(wp[1], u3, fmaf(wp[2], u4, ac[0][1][oc])));
                }
            }
            if (r5 >= 2) {
                int ky = r5 - 2;
                #pragma unroll
                for (int oc = 0; oc < 3; oc++) {
                    const float* wp = &scw[oc*27 + ic*9 + ky*3];
                    ac[1][0][oc] = fmaf(wp[0], u0, fmaf(wp[1], u1, fmaf(wp[2], u2, ac[1][0][oc])));
                    ac[1][1][oc] = fmaf(wp[0], u2, fmaf(wp[1], u3, fmaf(wp[2], u4, ac[1][1][oc])));
                }
            }
        }
    }

    float sg = g_inv_sigma;
    g_x[((b*3 + 0)*256 + oy)*256 + ox] = as0*sg + ssb[0];
    g_x[((b*3 + 1)*256 + oy)*256 + ox] = as1*sg + ssb[1];
    g_x[((b*3 + 2)*256 + oy)*256 + ox] = as2*sg + ssb[2];

    #pragma unroll
    for (int oc = 0; oc < 3; oc++) {
        #pragma unroll
        for (int sy = 0; sy < 2; sy++) {
            size_t o = ((size_t)(b*3 + oc)*512 + 2*oy + sy)*512 + 2*ox;
            *reinterpret_cast<float2*>(g_h0 + o) = make_float2(ac[sy][0][oc], ac[sy][1][oc]);
        }
    }
}

// ---------------- ctx stages 1..3: conv3x3(s2,p1) of relu(bn(in)), 2x2 outputs/thread ----------------
template<int STAGE>
__global__ void k_ctx4(const float* __restrict__ w,
                       const float* __restrict__ bias,
                       const float* __restrict__ bng,
                       const float* __restrict__ bnb) {
    constexpr int INH  = (STAGE == 1) ? 512 : (STAGE == 2) ? 256 : 128;
    constexpr int OUTW = INH / 2;
    constexpr int JW   = OUTW / 2;
    constexpr int LOGJ = (STAGE == 1) ? 7 : (STAGE == 2) ? 6 : 5;
    const float* in = (STAGE == 1) ? g_h0 : (STAGE == 2) ? g_h1 : g_h2;
    float* outp     = (STAGE == 1) ? g_h1 : (STAGE == 2) ? g_h2 : g_h3;

    __shared__ float sw[81];
    __shared__ float sb[3], sinv[3], sbb[3];
    for (int t = threadIdx.x; t < 81; t += blockDim.x) sw[t] = w[t];
    if (threadIdx.x < 3) {
        sb[threadIdx.x]   = bias[threadIdx.x];
        sinv[threadIdx.x] = bng[threadIdx.x] * rsqrtf(1.001f);
        sbb[threadIdx.x]  = bnb[threadIdx.x];
    }
    __syncthreads();

    int p  = blockIdx.x*blockDim.x + threadIdx.x;
    int jx = p & (JW - 1);
    int jy = p >> LOGJ;
    int b  = blockIdx.y;

    float ac[2][2][3];
    #pragma unroll
    for (int sy = 0; sy < 2; sy++)
        #pragma unroll
        for (int sx = 0; sx < 2; sx++)
            #pragma unroll
            for (int oc = 0; oc < 3; oc++)
                ac[sy][sx][oc] = sb[oc];

    bool left = (jx > 0);

    #pragma unroll
    for (int ic = 0; ic < 3; ic++) {
        const float* base = in + (size_t)(b*3 + ic)*INH*INH;
        float inv = sinv[ic], bb = sbb[ic];
        #pragma unroll
        for (int r5 = 0; r5 < 5; r5++) {
            int iy = 4*jy + r5 - 1;
            float u0, u1, u2, u3, u4;
            if (iy >= 0) {
                const float* rp = base + (size_t)iy*INH + 4*jx;
                float4 v4 = *reinterpret_cast<const float4*>(rp);
                float vm = left ? rp[-1] : 0.f;
                u0 = left ? fmaxf(fmaf(inv, vm, bb), 0.f) : 0.f;
                u1 = fmaxf(fmaf(inv, v4.x, bb), 0.f);
                u2 = fmaxf(fmaf(inv, v4.y, bb), 0.f);
                u3 = fmaxf(fmaf(inv, v4.z, bb), 0.f);
                u4 = fmaxf(fmaf(inv, v4.w, bb), 0.f);
            } else {
                u0 = u1 = u2 = u3 = u4 = 0.f;
            }
            if (r5 <= 2) {
                #pragma unroll
                for (int oc = 0; oc < 3; oc++) {
                    const float* wp = &sw[oc*27 + ic*9 + r5*3];
                    ac[0][0][oc] = fmaf(wp[0], u0, fmaf(wp[1], u1, fmaf(wp[2], u2, ac[0][0][oc])));
                    ac[0][1][oc] = fmaf(wp[0], u2, fmaf(wp[1], u3, fmaf(wp[2], u4, ac[0][1][oc])));
                }
            }
            if (r5 >= 2) {
                int ky = r5 - 2;
                #pragma unroll
                for (int oc = 0; oc < 3; oc++) {
                    const float* wp = &sw[oc*27 + ic*9 + ky*3];
                    ac[1][0][oc] = fmaf(wp[0], u0, fmaf(wp[1], u1, fmaf(wp[2], u2, ac[1][0][oc])));
                    ac[1][1][oc] = fmaf(wp[0], u2, fmaf(wp[1], u3, fmaf(wp[2], u4, ac[1][1][oc])));
                }
            }
        }
    }

    #pragma unroll
    for (int oc = 0; oc < 3; oc++) {
        #pragma unroll
        for (int sy = 0; sy < 2; sy++) {
            size_t o = ((size_t)(b*3 + oc)*OUTW + 2*jy + sy)*OUTW + 2*jx;
            *reinterpret_cast<float2*>(outp + o) = make_float2(ac[sy][0][oc], ac[sy][1][oc]);
        }
    }
}

// ---------------- pool conv: 2x2 stride 2 pad 0 ----------------
template<int STAGE>
__global__ void k_pool(const float* __restrict__ w,
                       const float* __restrict__ bias) {
    const float* in;
    float* out;
    int inH;
    if (STAGE == 0) { in = g_x;  out = g_p1; inH = 256; }
    else            { in = g_p1; out = g_p2; inH = 128; }
    const int inW = inH, outH = inH >> 1, outW = inW >> 1;

    __shared__ float sw[36];
    __shared__ float sb[3];
    for (int j = threadIdx.x; j < 36; j += blockDim.x) sw[j] = w[j];
    if (threadIdx.x < 3) sb[threadIdx.x] = bias[threadIdx.x];
    __syncthreads();

    int ox = threadIdx.x;
    if (ox >= outW) return;
    int oy = blockIdx.x;
    int b  = blockIdx.y;

    float a0 = sb[0], a1 = sb[1], a2 = sb[2];
    #pragma unroll
    for (int ic = 0; ic < 3; ic++) {
        const float* base = in + ((size_t)(b*3 + ic)*inH + 2*oy)*inW + 2*ox;
        float2 r0 = *reinterpret_cast<const float2*>(base);
        float2 r1 = *reinterpret_cast<const float2*>(base + inW);
        const float* w0 = &sw[(0*3 + ic)*4];
        const float* w1 = &sw[(1*3 + ic)*4];
        const float* w2 = &sw[(2*3 + ic)*4];
        a0 += w0[0]*r0.x + w0[1]*r0.y + w0[2]*r1.x + w0[3]*r1.y;
        a1 += w1[0]*r0.x + w1[1]*r0.y + w1[2]*r1.x + w1[3]*r1.y;
        a2 += w2[0]*r0.x + w2[1]*r0.y + w2[2]*r1.x + w2[3]*r1.y;
    }
    out[((b*3 + 0)*outH + oy)*outW + ox] = a0;
    out[((b*3 + 1)*outH + oy)*outW + ox] = a1;
    out[((b*3 + 2)*outH + oy)*outW + ox] = a2;
}

// ---------------- main fused pass: 2 pixels/thread (shared conditions) ----------------
__global__ void k_main2(const float* __restrict__ thresh,
                        const float* __restrict__ centers,
                        float* __restrict__ out) {
    __shared__ float sc[8];
    __shared__ unsigned int shist[8];
    __shared__ unsigned int sesti;
    __shared__ float sth[2];
    if (threadIdx.x < 8) { sc[threadIdx.x] = centers[threadIdx.x]; shist[threadIdx.x] = 0u; }
    if (threadIdx.x < 2) sth[threadIdx.x] = thresh[threadIdx.x];
    if (threadIdx.x == 0) sesti = 0u;
    __syncthreads();

    int t = blockIdx.x*blockDim.x + threadIdx.x;
    int i = 2*t;                      // pixels i, i+1 (same row, xp even)
    int xp = i & 255, y = (i >> 8) & 255, bc = i >> 16;
    float2 xv = *reinterpret_cast<const float2*>(g_x + i);
    int hi = bc*16384 + (y >> 1)*128 + (xp >> 1);   // same for both pixels
    int qi = bc*4096  + (y >> 2)*64  + (xp >> 2);   // same for both pixels
    float f1 = 0.5f*(tanhf(g_h2[hi]) + 1.0f);
    float f2 = 0.5f*(tanhf(g_h3[qi]) + 1.0f);
    bool c2 = f2 < sth[1];
    bool c1 = (!c2) && (f1 < sth[0]);
    bool c0 = !(c1 || c2);
    float rep = c1 ? g_p1[hi] : (c2 ? g_p2[qi] : 0.f);

    float xq0 = c0 ? xv.x : rep;
    float xq1 = c0 ? xv.y : rep;

    float r0, r1;
    int imin0 = 0, imin1 = 0;
    {
        float dd[8]; float dmin = 3.4e38f;
        #pragma unroll
        for (int k = 0; k < 8; k++) {
            float d = (xq0 - sc[k])*(xq0 - sc[k]);
            dd[k] = d;
            if (d < dmin) { dmin = d; imin0 = k; }
        }
        float s = 0.f, sn = 0.f;
        #pragma unroll
        for (int k = 0; k < 8; k++) {
            float e = __expf(dmin - dd[k]);
            s += e; sn = fmaf(e, sc[k], sn);
        }
        r0 = sn / s;
    }
    {
        float dd[8]; float dmin = 3.4e38f;
        #pragma unroll
        for (int k = 0; k < 8; k++) {
            float d = (xq1 - sc[k])*(xq1 - sc[k]);
            dd[k] = d;
            if (d < dmin) { dmin = d; imin1 = k; }
        }
        float s = 0.f, sn = 0.f;
        #pragma unroll
        for (int k = 0; k < 8; k++) {
            float e = __expf(dmin - dd[k]);
            s += e; sn = fmaf(e, sc[k], sn);
        }
        r1 = sn / s;
    }
    *reinterpret_cast<float2*>(out + i) = make_float2(r0, r1);

    unsigned int ev = 2u * (c0 ? 16u : (c1 ? 4u : 1u));
    if (c0) {                 // cond_0 => xq == x, so imin is argmin over x too
        atomicAdd(&shist[imin0], 1u);
        atomicAdd(&shist[imin1], 1u);
    }
    unsigned int wsum = __reduce_add_sync(0xffffffffu, ev);
    if ((threadIdx.x & 31) == 0) atomicAdd(&sesti, wsum);
    __syncthreads();
    if (threadIdx.x < 8 && shist[threadIdx.x]) atomicAdd(&g_counts[threadIdx.x], shist[threadIdx.x]);
    if (threadIdx.x == 0) atomicAdd(&g_esti16, sesti);
}

// ---------------- mask_1 histogram (half res) ----------------
__global__ void k_mask1(const float* __restrict__ thresh,
                        const float* __restrict__ centers) {
    __shared__ float sc[8];
    __shared__ unsigned int shist[8];
    __shared__ float sth[2];
    if (threadIdx.x < 8) { sc[threadIdx.x] = centers[threadIdx.x]; shist[threadIdx.x] = 0u; }
    if (threadIdx.x < 2) sth[threadIdx.x] = thresh[threadIdx.x];
    __syncthreads();

    int i = blockIdx.x*blockDim.x + threadIdx.x;
    if (i < NB*NC*128*128) {
        int xp = i & 127, y = (i >> 7) & 127, bc = i >> 14;
        float f1 = 0.5f*(tanhf(g_h2[i]) + 1.0f);
        float f2 = 0.5f*(tanhf(g_h3[bc*4096 + (y >> 1)*64 + (xp >> 1)]) + 1.0f);
        if (f2 >= sth[1] && f1 < sth[0]) {
            float p = g_p1[i];
            float dmin = 3.4e38f; int imin = 0;
            #pragma unroll
            for (int k = 0; k < 8; k++) {
                float t = p - sc[k];
                float d = t*t;
                if (d < dmin) { dmin = d; imin = k; }
            }
            atomicAdd(&shist[imin], 1u);
        }
    }
    __syncthreads();
    if (threadIdx.x < 8 && shist[threadIdx.x]) atomicAdd(&g_counts[threadIdx.x], shist[threadIdx.x]);
}

// ---------------- mask_2 histogram (quarter res) ----------------
__global__ void k_mask2(const float* __restrict__ thresh,
                        const float* __restrict__ centers) {
    __shared__ float sc[8];
    __shared__ unsigned int shist[8];
    __shared__ float sth1;
    if (threadIdx.x < 8) { sc[threadIdx.x] = centers[threadIdx.x]; shist[threadIdx.x] = 0u; }
    if (threadIdx.x == 0) sth1 = thresh[1];
    __syncthreads();

    int i = blockIdx.x*blockDim.x + threadIdx.x;
    if (i < NB*NC*64*64) {
        float f2 = 0.5f*(tanhf(g_h3[i]) + 1.0f);
        if (f2 < sth1) {
            float p = g_p2[i];
            float dmin = 3.4e38f; int imin = 0;
            #pragma unroll
            for (int k = 0; k < 8; k++) {
                float t = p - sc[k];
                float d = t*t;
                if (d < dmin) { dmin = d; imin = k; }
            }
            atomicAdd(&shist[imin], 1u);
        }
    }
    __syncthreads();
    if (threadIdx.x < 8 && shist[threadIdx.x]) atomicAdd(&g_counts[threadIdx.x], shist[threadIdx.x]);
}

// ---------------- finalize scalars ----------------
__global__ void k_fin(float* __restrict__ out, int soft_n) {
    if (threadIdx.x == 0 && blockIdx.x == 0) {
        double tot = 0.0;
        for (int k = 0; k < 8; k++) tot += (double)g_counts[k];
        double c[8];
        double mean = 0.0;
        for (int k = 0; k < 8; k++) { c[k] = (double)g_counts[k] / tot; mean += c[k]; }
        mean /= 8.0;
        double var = 0.0;
        for (int k = 0; k < 8; k++) { double d = c[k] - mean; var += d*d; }
        double stdv = sqrt(var / 7.0);
        double esti = (double)g_esti16 / 16.0;
        double cr = (1.0/16.0) * esti / (256.0*256.0*3.0*8.0);
        out[soft_n]     = (float)cr;
        out[soft_n + 1] = (float)stdv;
    }
}

// ---------------- launch ----------------
extern "C" void kernel_launch(void* const* d_in, const int* in_sizes, int n_in,
                              void* d_out, int out_size) {
    const float* x_init   = (const float*)d_in[0];
    const float* thresh   = (const float*)d_in[1];
    const float* sample_w = (const float*)d_in[2];
    const float* sample_b = (const float*)d_in[3];
    const float* centers  = (const float*)d_in[4];
    const float* pool1_w  = (const float*)d_in[5];
    const float* pool1_b  = (const float*)d_in[6];
    const float* pool2_w  = (const float*)d_in[7];
    const float* pool2_b  = (const float*)d_in[8];
    const float* ctx_w    = (const float*)d_in[9];
    const float* ctx_b    = (const float*)d_in[10];
    const float* bng      = (const float*)d_in[11];
    const float* bnb      = (const float*)d_in[12];
    float* out = (float*)d_out;
    int soft_n = out_size - 2;

    k_init<<<1, 32>>>(sample_w);
    k_fused<<<dim3(256, 8), 256>>>(x_init, sample_w, sample_b,
                                   ctx_w + 0*81, ctx_b + 0*3, bng + 0*3, bnb + 0*3);
    k_ctx4<1><<<dim3(64, 8), 256>>>(ctx_w + 1*81, ctx_b + 1*3, bng + 1*3, bnb + 1*3);
    k_ctx4<2><<<dim3(16, 8), 256>>>(ctx_w + 2*81, ctx_b + 2*3, bng + 2*3, bnb + 2*3);
    k_ctx4<3><<<dim3(4, 8),  256>>>(ctx_w + 3*81, ctx_b + 3*3, bng + 3*3, bnb + 3*3);
    k_pool<0><<<dim3(128, 8), 128>>>(pool1_w, pool1_b);
    k_pool<1><<<dim3(64, 8),  64>>> (pool2_w, pool2_b);
    k_main2<<<(NB*NC*256*256/2 + 255)/256, 256>>>(thresh, centers, out);
    k_mask1<<<(NB*NC*128*128 + 255)/256, 256>>>(thresh, centers);
    k_mask2<<<(NB*NC*64*64 + 255)/256, 256>>>(thresh, centers);
    k_fin<<<1, 32>>>(out, soft_n);
}

// round 6
// speedup vs baseline: 1.6218x; 1.0867x over previous
#include <cuda_runtime.h>
#include <math.h>

#define NB 8
#define NC 3

// ---------------- scratch (device globals; no runtime allocation) ----------------
__device__ float g_x [NB*NC*256*256];   // sample conv output
__device__ float g_h0[NB*NC*512*512];   // ctx stage 0 out
__device__ float g_h1[NB*NC*256*256];   // ctx stage 1 out
__device__ float g_h2[NB*NC*128*128];   // ctx stage 2 out (pre-tanh feat_1)
__device__ float g_h3[NB*NC*64*64];     // ctx stage 3 out (pre-tanh feat_2)
__device__ float g_p1[NB*NC*128*128];
__device__ float g_p2[NB*NC*64*64];
__device__ float g_inv_sigma;
__device__ unsigned int g_counts[8];
__device__ unsigned int g_esti16;       // esti_size in units of 1/16 (exact integer)
__device__ unsigned int g_done = 0;     // last-block ticket for in-kernel finalize

// ---------------- init: zero accumulators + spectral norm of sample_w ----------------
__global__ void k_init(const float* __restrict__ w) {
    __shared__ double sG[9];
    int t = threadIdx.x;
    if (t < 8) g_counts[t] = 0u;
    if (t == 0) g_esti16 = 0u;
    if (t < 9) {
        int i = t / 3, j = t % 3;
        double s0 = 0.0, s1 = 0.0, s2 = 0.0, s3 = 0.0;
        #pragma unroll
        for (int k = 0; k < 48; k += 4) {
            s0 += (double)w[i*48 + k + 0] * (double)w[j*48 + k + 0];
            s1 += (double)w[i*48 + k + 1] * (double)w[j*48 + k + 1];
            s2 += (double)w[i*48 + k + 2] * (double)w[j*48 + k + 2];
            s3 += (double)w[i*48 + k + 3] * (double)w[j*48 + k + 3];
        }
        sG[t] = (s0 + s1) + (s2 + s3);
    }
    __syncthreads();
    if (t == 0) {
        double g00 = sG[0], g01 = sG[1], g02 = sG[2];
        double g11 = sG[4], g12 = sG[5], g22 = sG[8];
        double q  = (g00 + g11 + g22) / 3.0;
        double p1 = g01*g01 + g02*g02 + g12*g12;
        double d0 = g00 - q, d1 = g11 - q, d2 = g22 - q;
        double p2 = d0*d0 + d1*d1 + d2*d2 + 2.0*p1;
        double lam;
        if (p2 <= 1e-300) {
            lam = q;
        } else {
            double p = sqrt(p2 / 6.0);
            double ip = 1.0 / p;
            double b00 = d0*ip, b11 = d1*ip, b22 = d2*ip;
            double b01 = g01*ip, b02 = g02*ip, b12 = g12*ip;
            double detB = b00*(b11*b22 - b12*b12)
                        - b01*(b01*b22 - b12*b02)
                        + b02*(b01*b12 - b11*b02);
            double r = 0.5 * detB;
            r = fmin(1.0, fmax(-1.0, r));
            double phi = acos(r) / 3.0;
            lam = q + 2.0*p*cos(phi);
        }
        g_inv_sigma = (float)(1.0 / sqrt(lam));
    }
}

// ---------------- fused: sample conv (4x4 s4) + ctx stage 0 (3x3 s2 p1) ----------------
__global__ void k_fused(const float* __restrict__ x,
                        const float* __restrict__ samw,
                        const float* __restrict__ samb,
                        const float* __restrict__ cw,
                        const float* __restrict__ cb,
                        const float* __restrict__ bng,
                        const float* __restrict__ bnb) {
    __shared__ float ssw[144], ssb[3];
    __shared__ float scw[81], scb[3], sinv[3], sbb[3];
    int tid = threadIdx.x;
    if (tid < 144) ssw[tid] = samw[tid];
    if (tid < 81)  scw[tid] = cw[tid];
    if (tid < 3) {
        ssb[tid]  = samb[tid];
        scb[tid]  = cb[tid];
        sinv[tid] = bng[tid] * rsqrtf(1.001f);
        sbb[tid]  = bnb[tid];
    }
    __syncthreads();

    int ox = threadIdx.x;      // 0..255
    int oy = blockIdx.x;       // 0..255
    int b  = blockIdx.y;

    float as0 = 0.f, as1 = 0.f, as2 = 0.f;
    float ac[2][2][3];
    #pragma unroll
    for (int sy = 0; sy < 2; sy++)
        #pragma unroll
        for (int sx = 0; sx < 2; sx++)
            #pragma unroll
            for (int oc = 0; oc < 3; oc++)
                ac[sy][sx][oc] = scb[oc];

    bool left = (ox > 0);

    #pragma unroll
    for (int ic = 0; ic < 3; ic++) {
        const float* base = x + (size_t)(b*3 + ic)*1024*1024;
        float inv = sinv[ic], bb = sbb[ic];
        #pragma unroll
        for (int r5 = 0; r5 < 5; r5++) {
            int iy = 4*oy + r5 - 1;
            float u0, u1, u2, u3, u4;
            if (iy >= 0) {
                const float* rp = base + (size_t)iy*1024 + 4*ox;
                float4 v4 = *reinterpret_cast<const float4*>(rp);
                float vm = left ? rp[-1] : 0.f;
                u0 = left ? fmaxf(fmaf(inv, vm, bb), 0.f) : 0.f;
                u1 = fmaxf(fmaf(inv, v4.x, bb), 0.f);
                u2 = fmaxf(fmaf(inv, v4.y, bb), 0.f);
                u3 = fmaxf(fmaf(inv, v4.z, bb), 0.f);
                u4 = fmaxf(fmaf(inv, v4.w, bb), 0.f);
                if (r5 >= 1) {
                    int ky = r5 - 1;
                    const float* w0 = &ssw[(0*3 + ic)*16 + ky*4];
                    const float* w1 = &ssw[(1*3 + ic)*16 + ky*4];
                    const float* w2 = &ssw[(2*3 + ic)*16 + ky*4];
                    as0 += w0[0]*v4.x + w0[1]*v4.y + w0[2]*v4.z + w0[3]*v4.w;
                    as1 += w1[0]*v4.x + w1[1]*v4.y + w1[2]*v4.z + w1[3]*v4.w;
                    as2 += w2[0]*v4.x + w2[1]*v4.y + w2[2]*v4.z + w2[3]*v4.w;
                }
            } else {
                u0 = u1 = u2 = u3 = u4 = 0.f;
            }
            if (r5 <= 2) {
                #pragma unroll
                for (int oc = 0; oc < 3; oc++) {
                    const float* wp = &scw[oc*27 + ic*9 + r5*3];
                    ac[0][0][oc] = fmaf(wp[0], u0, fmaf(wp[1], u1, fmaf(wp[2], u2, ac[0][0][oc])));
                    ac[0][1][oc] = fmaf(wp[0], u2, fmaf(wp[1], u3, fmaf(wp[2], u4, ac[0][1][oc])));
                }
            }
            if (r5 >= 2) {
                int ky = r5 - 2;
                #pragma unroll
                for (int oc = 0; oc < 3; oc++) {
                    const float* wp = &scw[oc*27 + ic*9 + ky*3];
                    ac[1][0][oc] = fmaf(wp[0], u0, fmaf(wp[1], u1, fmaf(wp[2], u2, ac[1][0][oc])));
                    ac[1][1][oc] = fmaf(wp[0], u2, fmaf(wp[1], u3, fmaf(wp[2], u4, ac[1][1][oc])));
                }
            }
        }
    }

    float sg = g_inv_sigma;
    g_x[((b*3 + 0)*256 + oy)*256 + ox] = as0*sg + ssb[0];
    g_x[((b*3 + 1)*256 + oy)*256 + ox] = as1*sg + ssb[1];
    g_x[((b*3 + 2)*256 + oy)*256 + ox] = as2*sg + ssb[2];

    #pragma unroll
    for (int oc = 0; oc < 3; oc++) {
        #pragma unroll
        for (int sy = 0; sy < 2; sy++) {
            size_t o = ((size_t)(b*3 + oc)*512 + 2*oy + sy)*512 + 2*ox;
            *reinterpret_cast<float2*>(g_h0 + o) = make_float2(ac[sy][0][oc], ac[sy][1][oc]);
        }
    }
}

// ---------------- ctx stage 1: 2x2 outputs/thread (large stage, works well) ----------------
__global__ void k_ctx1(const float* __restrict__ w,
                       const float* __restrict__ bias,
                       const float* __restrict__ bng,
                       const float* __restrict__ bnb) {
    constexpr int INH  = 512;
    constexpr int OUTW = 256;
    constexpr int JW   = 128;
    constexpr int LOGJ = 7;
    const float* in = g_h0;
    float* outp     = g_h1;

    __shared__ float sw[81];
    __shared__ float sb[3], sinv[3], sbb[3];
    for (int t = threadIdx.x; t < 81; t += blockDim.x) sw[t] = w[t];
    if (threadIdx.x < 3) {
        sb[threadIdx.x]   = bias[threadIdx.x];
        sinv[threadIdx.x] = bng[threadIdx.x] * rsqrtf(1.001f);
        sbb[threadIdx.x]  = bnb[threadIdx.x];
    }
    __syncthreads();

    int p  = blockIdx.x*blockDim.x + threadIdx.x;
    int jx = p & (JW - 1);
    int jy = p >> LOGJ;
    int b  = blockIdx.y;

    float ac[2][2][3];
    #pragma unroll
    for (int sy = 0; sy < 2; sy++)
        #pragma unroll
        for (int sx = 0; sx < 2; sx++)
            #pragma unroll
            for (int oc = 0; oc < 3; oc++)
                ac[sy][sx][oc] = sb[oc];

    bool left = (jx > 0);

    #pragma unroll
    for (int ic = 0; ic < 3; ic++) {
        const float* base = in + (size_t)(b*3 + ic)*INH*INH;
        float inv = sinv[ic], bb = sbb[ic];
        #pragma unroll
        for (int r5 = 0; r5 < 5; r5++) {
            int iy = 4*jy + r5 - 1;
            float u0, u1, u2, u3, u4;
            if (iy >= 0) {
                const float* rp = base + (size_t)iy*INH + 4*jx;
                float4 v4 = *reinterpret_cast<const float4*>(rp);
                float vm = left ? rp[-1] : 0.f;
                u0 = left ? fmaxf(fmaf(inv, vm, bb), 0.f) : 0.f;
                u1 = fmaxf(fmaf(inv, v4.x, bb), 0.f);
                u2 = fmaxf(fmaf(inv, v4.y, bb), 0.f);
                u3 = fmaxf(fmaf(inv, v4.z, bb), 0.f);
                u4 = fmaxf(fmaf(inv, v4.w, bb), 0.f);
            } else {
                u0 = u1 = u2 = u3 = u4 = 0.f;
            }
            if (r5 <= 2) {
                #pragma unroll
                for (int oc = 0; oc < 3; oc++) {
                    const float* wp = &sw[oc*27 + ic*9 + r5*3];
                    ac[0][0][oc] = fmaf(wp[0], u0, fmaf(wp[1], u1, fmaf(wp[2], u2, ac[0][0][oc])));
                    ac[0][1][oc] = fmaf(wp[0], u2, fmaf(wp[1], u3, fmaf(wp[2], u4, ac[0][1][oc])));
                }
            }
            if (r5 >= 2) {
                int ky = r5 - 2;
                #pragma unroll
                for (int oc = 0; oc < 3; oc++) {
                    const float* wp = &sw[oc*27 + ic*9 + ky*3];
                    ac[1][0][oc] = fmaf(wp[0], u0, fmaf(wp[1], u1, fmaf(wp[2], u2, ac[1][0][oc])));
                    ac[1][1][oc] = fmaf(wp[0], u2, fmaf(wp[1], u3, fmaf(wp[2], u4, ac[1][1][oc])));
                }
            }
        }
    }

    #pragma unroll
    for (int oc = 0; oc < 3; oc++) {
        #pragma unroll
        for (int sy = 0; sy < 2; sy++) {
            size_t o = ((size_t)(b*3 + oc)*OUTW + 2*jy + sy)*OUTW + 2*jx;
            *reinterpret_cast<float2*>(outp + o) = make_float2(ac[sy][0][oc], ac[sy][1][oc]);
        }
    }
}

// ---------------- ctx stages 2/3: per-pixel (3ch) for max parallelism ----------------
template<int STAGE>
__global__ void k_ctx_px(const float* __restrict__ w,
                         const float* __restrict__ bias,
                         const float* __restrict__ bng,
                         const float* __restrict__ bnb) {
    constexpr int INH  = (STAGE == 2) ? 256 : 128;
    constexpr int OUTW = INH / 2;
    constexpr int LOG  = (STAGE == 2) ? 7 : 6;
    const float* in = (STAGE == 2) ? g_h1 : g_h2;
    float* outp     = (STAGE == 2) ? g_h2 : g_h3;

    __shared__ float sw[81];
    __shared__ float sb[3], sinv[3], sbb[3];
    for (int t = threadIdx.x; t < 81; t += blockDim.x) sw[t] = w[t];
    if (threadIdx.x < 3) {
        sb[threadIdx.x]   = bias[threadIdx.x];
        sinv[threadIdx.x] = bng[threadIdx.x] * rsqrtf(1.001f);
        sbb[threadIdx.x]  = bnb[threadIdx.x];
    }
    __syncthreads();

    int i  = blockIdx.x*blockDim.x + threadIdx.x;
    int ox = i & (OUTW - 1);
    int oy = (i >> LOG) & (OUTW - 1);
    int b  = i >> (2*LOG);

    float a0 = sb[0], a1 = sb[1], a2 = sb[2];
    bool left = (ox > 0);
    #pragma unroll
    for (int ic = 0; ic < 3; ic++) {
        const float* base = in + (size_t)(b*3 + ic)*INH*INH;
        float inv = sinv[ic], bb = sbb[ic];
        #pragma unroll
        for (int r = 0; r < 3; r++) {
            int iy = 2*oy + r - 1;
            float uL = 0.f, u0 = 0.f, u1 = 0.f;
            if (iy >= 0) {
                const float* rp = base + (size_t)iy*INH + 2*ox;
                float2 v = *reinterpret_cast<const float2*>(rp);
                u0 = fmaxf(fmaf(inv, v.x, bb), 0.f);
                u1 = fmaxf(fmaf(inv, v.y, bb), 0.f);
                if (left) uL = fmaxf(fmaf(inv, rp[-1], bb), 0.f);
            }
            const float* wp = &sw[ic*9 + r*3];
            a0 = fmaf(wp[0],  uL, fmaf(wp[1],  u0, fmaf(wp[2],  u1, a0)));
            a1 = fmaf(wp[27], uL, fmaf(wp[28], u0, fmaf(wp[29], u1, a1)));
            a2 = fmaf(wp[54], uL, fmaf(wp[55], u0, fmaf(wp[56], u1, a2)));
        }
    }
    outp[((b*3 + 0)*OUTW + oy)*OUTW + ox] = a0;
    outp[((b*3 + 1)*OUTW + oy)*OUTW + ox] = a1;
    outp[((b*3 + 2)*OUTW + oy)*OUTW + ox] = a2;
}

// ---------------- fused pools: thread computes 2x2 p1 block + 1 p2 pixel ----------------
__global__ void k_poolc(const float* __restrict__ w1, const float* __restrict__ b1,
                        const float* __restrict__ w2, const float* __restrict__ b2) {
    __shared__ float sw1[36], sw2[36], sb1[3], sb2[3];
    for (int t = threadIdx.x; t < 36; t += blockDim.x) { sw1[t] = w1[t]; sw2[t] = w2[t]; }
    if (threadIdx.x < 3) { sb1[threadIdx.x] = b1[threadIdx.x]; sb2[threadIdx.x] = b2[threadIdx.x]; }
    __syncthreads();

    int i  = blockIdx.x*blockDim.x + threadIdx.x;
    int ox = i & 63;
    int oy = (i >> 6) & 63;
    int b  = i >> 12;

    float p1v[2][2][3];
    #pragma unroll
    for (int sy = 0; sy < 2; sy++)
        #pragma unroll
        for (int sx = 0; sx < 2; sx++)
            #pragma unroll
            for (int mc = 0; mc < 3; mc++)
                p1v[sy][sx][mc] = sb1[mc];

    #pragma unroll
    for (int ic = 0; ic < 3; ic++) {
        const float* base = g_x + (size_t)(b*3 + ic)*65536 + (size_t)(4*oy)*256 + 4*ox;
        float rx[4][4];
        #pragma unroll
        for (int r = 0; r < 4; r++) {
            float4 v = *reinterpret_cast<const float4*>(base + r*256);
            rx[r][0] = v.x; rx[r][1] = v.y; rx[r][2] = v.z; rx[r][3] = v.w;
        }
        #pragma unroll
        for (int mc = 0; mc < 3; mc++) {
            const float* wp = &sw1[mc*12 + ic*4];
            #pragma unroll
            for (int sy = 0; sy < 2; sy++)
                #pragma unroll
                for (int sx = 0; sx < 2; sx++)
                    p1v[sy][sx][mc] += wp[0]*rx[2*sy][2*sx]   + wp[1]*rx[2*sy][2*sx+1]
                                     + wp[2]*rx[2*sy+1][2*sx] + wp[3]*rx[2*sy+1][2*sx+1];
        }
    }

    // store p1
    #pragma unroll
    for (int mc = 0; mc < 3; mc++)
        #pragma unroll
        for (int sy = 0; sy < 2; sy++) {
            size_t o = ((size_t)(b*3 + mc)*128 + 2*oy + sy)*128 + 2*ox;
            *reinterpret_cast<float2*>(g_p1 + o) = make_float2(p1v[sy][0][mc], p1v[sy][1][mc]);
        }

    // p2 from p1 block
    #pragma unroll
    for (int oc = 0; oc < 3; oc++) {
        float a = sb2[oc];
        #pragma unroll
        for (int mc = 0; mc < 3; mc++) {
            const float* wp = &sw2[oc*12 + mc*4];
            a += wp[0]*p1v[0][0][mc] + wp[1]*p1v[0][1][mc]
               + wp[2]*p1v[1][0][mc] + wp[3]*p1v[1][1][mc];
        }
        g_p2[((size_t)(b*3 + oc)*64 + oy)*64 + ox] = a;
    }
}

// ---------------- mega: soft-VQ main (2 px/thread) + mask1 + mask2 + finalize ----------------
__global__ void k_mega(const float* __restrict__ thresh,
                       const float* __restrict__ centers,
                       float* __restrict__ out, int soft_n) {
    __shared__ float sc[8];
    __shared__ unsigned int shist[8];
    __shared__ unsigned int sesti;
    __shared__ float sth[2];
    int tid = threadIdx.x;
    if (tid < 8) { sc[tid] = centers[tid]; shist[tid] = 0u; }
    if (tid < 2) sth[tid] = thresh[tid];
    if (tid == 0) sesti = 0u;
    __syncthreads();

    int t = blockIdx.x*blockDim.x + tid;     // 0 .. 786431
    unsigned int ev;

    // ---- main part: pixels 2t, 2t+1 ----
    {
        int i = 2*t;
        int xp = i & 255, y = (i >> 8) & 255, bc = i >> 16;
        float2 xv = *reinterpret_cast<const float2*>(g_x + i);
        int hi = bc*16384 + (y >> 1)*128 + (xp >> 1);
        int qi = bc*4096  + (y >> 2)*64  + (xp >> 2);
        float f1 = 0.5f*(tanhf(g_h2[hi]) + 1.0f);
        float f2 = 0.5f*(tanhf(g_h3[qi]) + 1.0f);
        bool c2 = f2 < sth[1];
        bool c1 = (!c2) && (f1 < sth[0]);
        bool c0 = !(c1 || c2);
        float rep = c1 ? g_p1[hi] : (c2 ? g_p2[qi] : 0.f);
        float xq0 = c0 ? xv.x : rep;
        float xq1 = c0 ? xv.y : rep;

        float r0, r1;
        int imin0 = 0, imin1 = 0;
        {
            float dd[8]; float dmin = 3.4e38f;
            #pragma unroll
            for (int k = 0; k < 8; k++) {
                float d = (xq0 - sc[k])*(xq0 - sc[k]);
                dd[k] = d;
                if (d < dmin) { dmin = d; imin0 = k; }
            }
            float s = 0.f, sn = 0.f;
            #pragma unroll
            for (int k = 0; k < 8; k++) {
                float e = __expf(dmin - dd[k]);
                s += e; sn = fmaf(e, sc[k], sn);
            }
            r0 = sn / s;
        }
        {
            float dd[8]; float dmin = 3.4e38f;
            #pragma unroll
            for (int k = 0; k < 8; k++) {
                float d = (xq1 - sc[k])*(xq1 - sc[k]);
                dd[k] = d;
                if (d < dmin) { dmin = d; imin1 = k; }
            }
            float s = 0.f, sn = 0.f;
            #pragma unroll
            for (int k = 0; k < 8; k++) {
                float e = __expf(dmin - dd[k]);
                s += e; sn = fmaf(e, sc[k], sn);
            }
            r1 = sn / s;
        }
        *reinterpret_cast<float2*>(out + i) = make_float2(r0, r1);

        ev = 2u * (c0 ? 16u : (c1 ? 4u : 1u));
        if (c0) {
            atomicAdd(&shist[imin0], 1u);
            atomicAdd(&shist[imin1], 1u);
        }
    }

    // ---- mask1 part ----
    if (t < NB*NC*128*128) {
        int xp = t & 127, y = (t >> 7) & 127, bc = t >> 14;
        float f1 = 0.5f*(tanhf(g_h2[t]) + 1.0f);
        float f2 = 0.5f*(tanhf(g_h3[bc*4096 + (y >> 1)*64 + (xp >> 1)]) + 1.0f);
        if (f2 >= sth[1] && f1 < sth[0]) {
            float p = g_p1[t];
            float dmin = 3.4e38f; int imin = 0;
            #pragma unroll
            for (int k = 0; k < 8; k++) {
                float d = (p - sc[k])*(p - sc[k]);
                if (d < dmin) { dmin = d; imin = k; }
            }
            atomicAdd(&shist[imin], 1u);
        }
    }

    // ---- mask2 part ----
    if (t < NB*NC*64*64) {
        float f2 = 0.5f*(tanhf(g_h3[t]) + 1.0f);
        if (f2 < sth[1]) {
            float p = g_p2[t];
            float dmin = 3.4e38f; int imin = 0;
            #pragma unroll
            for (int k = 0; k < 8; k++) {
                float d = (p - sc[k])*(p - sc[k]);
                if (d < dmin) { dmin = d; imin = k; }
            }
            atomicAdd(&shist[imin], 1u);
        }
    }

    // ---- block reductions + flush ----
    unsigned int wsum = __reduce_add_sync(0xffffffffu, ev);
    if ((tid & 31) == 0) atomicAdd(&sesti, wsum);
    __syncthreads();
    if (tid < 8) {
        if (shist[tid]) atomicAdd(&g_counts[tid], shist[tid]);
        if (tid == 0) atomicAdd(&g_esti16, sesti);
        __threadfence();
    }
    __syncthreads();

    // ---- last-block finalize ----
    if (tid == 0) {
        unsigned int ticket = atomicAdd(&g_done, 1u);
        if (ticket == gridDim.x - 1) {
            double tot = 0.0;
            double c[8];
            for (int k = 0; k < 8; k++) {
                c[k] = (double)atomicAdd(&g_counts[k], 0u);
                tot += c[k];
            }
            double mean = 0.0;
            for (int k = 0; k < 8; k++) { c[k] /= tot; mean += c[k]; }
            mean /= 8.0;
            double var = 0.0;
            for (int k = 0; k < 8; k++) { double d = c[k] - mean; var += d*d; }
            double stdv = sqrt(var / 7.0);
            double esti = (double)atomicAdd(&g_esti16, 0u) / 16.0;
            double cr = (1.0/16.0) * esti / (256.0*256.0*3.0*8.0);
            out[soft_n]     = (float)cr;
            out[soft_n + 1] = (float)stdv;
            atomicExch(&g_done, 0u);    // reset for next replay
        }
    }
}

// ---------------- launch ----------------
extern "C" void kernel_launch(void* const* d_in, const int* in_sizes, int n_in,
                              void* d_out, int out_size) {
    const float* x_init   = (const float*)d_in[0];
    const float* thresh   = (const float*)d_in[1];
    const float* sample_w = (const float*)d_in[2];
    const float* sample_b = (const float*)d_in[3];
    const float* centers  = (const float*)d_in[4];
    const float* pool1_w  = (const float*)d_in[5];
    const float* pool1_b  = (const float*)d_in[6];
    const float* pool2_w  = (const float*)d_in[7];
    const float* pool2_b  = (const float*)d_in[8];
    const float* ctx_w    = (const float*)d_in[9];
    const float* ctx_b    = (const float*)d_in[10];
    const float* bng      = (const float*)d_in[11];
    const float* bnb      = (const float*)d_in[12];
    float* out = (float*)d_out;
    int soft_n = out_size - 2;

    k_init<<<1, 32>>>(sample_w);
    k_fused<<<dim3(256, 8), 256>>>(x_init, sample_w, sample_b,
                                   ctx_w + 0*81, ctx_b + 0*3, bng + 0*3, bnb + 0*3);
    k_poolc<<<256, 128>>>(pool1_w, pool1_b, pool2_w, pool2_b);
    k_ctx1<<<dim3(64, 8), 256>>>(ctx_w + 1*81, ctx_b + 1*3, bng + 1*3, bnb + 1*3);
    k_ctx_px<2><<<512, 256>>>(ctx_w + 2*81, ctx_b + 2*3, bng + 2*3, bnb + 2*3);
    k_ctx_px<3><<<256, 128>>>(ctx_w + 3*81, ctx_b + 3*3, bng + 3*3, bnb + 3*3);
    k_mega<<<3072, 256>>>(thresh, centers, out, soft_n);
}

// round 7
// speedup vs baseline: 1.8690x; 1.1525x over previous
#include <cuda_runtime.h>
#include <math.h>

#define NB 8
#define NC 3

// ---------------- scratch (device globals; no runtime allocation) ----------------
__device__ float g_x [NB*NC*256*256];   // UNSCALED sample conv output (no sigma, no bias)
__device__ float g_h0[NB*NC*512*512];
__device__ float g_h1[NB*NC*256*256];
__device__ float g_h2[NB*NC*128*128];
__device__ float g_h3[NB*NC*64*64];
__device__ float g_p1[NB*NC*128*128];
__device__ float g_p2[NB*NC*64*64];
__device__ float g_inv_sigma;
__device__ unsigned int g_counts[8];    // zero-init at load; reset by mega finalize
__device__ unsigned int g_esti16;
__device__ unsigned int g_done = 0;

// ---------------- fused: sample conv (4x4 s4, unscaled) + ctx stage 0 ----------------
__global__ void k_fused(const float* __restrict__ x,
                        const float* __restrict__ samw,
                        const float* __restrict__ cw,
                        const float* __restrict__ cb,
                        const float* __restrict__ bng,
                        const float* __restrict__ bnb) {
    __shared__ float ssw[144];
    __shared__ float scw[81], scb[3], sinv[3], sbb[3];
    int tid = threadIdx.x;
    if (tid < 144) ssw[tid] = samw[tid];
    if (tid < 81)  scw[tid] = cw[tid];
    if (tid < 3) {
        scb[tid]  = cb[tid];
        sinv[tid] = bng[tid] * rsqrtf(1.001f);
        sbb[tid]  = bnb[tid];
    }
    __syncthreads();

    int ox = threadIdx.x;
    int oy = blockIdx.x;
    int b  = blockIdx.y;

    float as0 = 0.f, as1 = 0.f, as2 = 0.f;
    float ac[2][2][3];
    #pragma unroll
    for (int sy = 0; sy < 2; sy++)
        #pragma unroll
        for (int sx = 0; sx < 2; sx++)
            #pragma unroll
            for (int oc = 0; oc < 3; oc++)
                ac[sy][sx][oc] = scb[oc];

    bool left = (ox > 0);

    #pragma unroll
    for (int ic = 0; ic < 3; ic++) {
        const float* base = x + (size_t)(b*3 + ic)*1024*1024;
        float inv = sinv[ic], bb = sbb[ic];
        #pragma unroll
        for (int r5 = 0; r5 < 5; r5++) {
            int iy = 4*oy + r5 - 1;
            float u0, u1, u2, u3, u4;
            if (iy >= 0) {
                const float* rp = base + (size_t)iy*1024 + 4*ox;
                float4 v4 = *reinterpret_cast<const float4*>(rp);
                float vm = left ? rp[-1] : 0.f;
                u0 = left ? fmaxf(fmaf(inv, vm, bb), 0.f) : 0.f;
                u1 = fmaxf(fmaf(inv, v4.x, bb), 0.f);
                u2 = fmaxf(fmaf(inv, v4.y, bb), 0.f);
                u3 = fmaxf(fmaf(inv, v4.z, bb), 0.f);
                u4 = fmaxf(fmaf(inv, v4.w, bb), 0.f);
                if (r5 >= 1) {
                    int ky = r5 - 1;
                    const float* w0 = &ssw[(0*3 + ic)*16 + ky*4];
                    const float* w1 = &ssw[(1*3 + ic)*16 + ky*4];
                    const float* w2 = &ssw[(2*3 + ic)*16 + ky*4];
                    as0 += w0[0]*v4.x + w0[1]*v4.y + w0[2]*v4.z + w0[3]*v4.w;
                    as1 += w1[0]*v4.x + w1[1]*v4.y + w1[2]*v4.z + w1[3]*v4.w;
                    as2 += w2[0]*v4.x + w2[1]*v4.y + w2[2]*v4.z + w2[3]*v4.w;
                }
            } else {
                u0 = u1 = u2 = u3 = u4 = 0.f;
            }
            if (r5 <= 2) {
                #pragma unroll
                for (int oc = 0; oc < 3; oc++) {
                    const float* wp = &scw[oc*27 + ic*9 + r5*3];
                    ac[0][0][oc] = fmaf(wp[0], u0, fmaf(wp[1], u1, fmaf(wp[2], u2, ac[0][0][oc])));
                    ac[0][1][oc] = fmaf(wp[0], u2, fmaf(wp[1], u3, fmaf(wp[2], u4, ac[0][1][oc])));
                }
            }
            if (r5 >= 2) {
                int ky = r5 - 2;
                #pragma unroll
                for (int oc = 0; oc < 3; oc++) {
                    const float* wp = &scw[oc*27 + ic*9 + ky*3];
                    ac[1][0][oc] = fmaf(wp[0], u0, fmaf(wp[1], u1, fmaf(wp[2], u2, ac[1][0][oc])));
                    ac[1][1][oc] = fmaf(wp[0], u2, fmaf(wp[1], u3, fmaf(wp[2], u4, ac[1][1][oc])));
                }
            }
        }
    }

    // store UNSCALED sample conv (consumers apply *inv_sigma + bias)
    g_x[((b*3 + 0)*256 + oy)*256 + ox] = as0;
    g_x[((b*3 + 1)*256 + oy)*256 + ox] = as1;
    g_x[((b*3 + 2)*256 + oy)*256 + ox] = as2;

    #pragma unroll
    for (int oc = 0; oc < 3; oc++) {
        #pragma unroll
        for (int sy = 0; sy < 2; sy++) {
            size_t o = ((size_t)(b*3 + oc)*512 + 2*oy + sy)*512 + 2*ox;
            *reinterpret_cast<float2*>(g_h0 + o) = make_float2(ac[sy][0][oc], ac[sy][1][oc]);
        }
    }
}

// ---------------- per-pixel ctx conv body (stages 1..3) ----------------
template<int STAGE>
__device__ __forceinline__ void ctx_px_body(int i,
                                            const float* sw, const float* sb,
                                            const float* sinv, const float* sbb) {
    constexpr int INH  = (STAGE == 1) ? 512 : (STAGE == 2) ? 256 : 128;
    constexpr int OUTW = INH / 2;
    constexpr int LOG  = (STAGE == 1) ? 8 : (STAGE == 2) ? 7 : 6;
    const float* in = (STAGE == 1) ? g_h0 : (STAGE == 2) ? g_h1 : g_h2;
    float* outp     = (STAGE == 1) ? g_h1 : (STAGE == 2) ? g_h2 : g_h3;

    int ox = i & (OUTW - 1);
    int oy = (i >> LOG) & (OUTW - 1);
    int b  = i >> (2*LOG);

    float a0 = sb[0], a1 = sb[1], a2 = sb[2];
    bool left = (ox > 0);
    #pragma unroll
    for (int ic = 0; ic < 3; ic++) {
        const float* base = in + (size_t)(b*3 + ic)*INH*INH;
        float inv = sinv[ic], bb = sbb[ic];
        #pragma unroll
        for (int r = 0; r < 3; r++) {
            int iy = 2*oy + r - 1;
            float uL = 0.f, u0 = 0.f, u1 = 0.f;
            if (iy >= 0) {
                const float* rp = base + (size_t)iy*INH + 2*ox;
                float2 v = *reinterpret_cast<const float2*>(rp);
                u0 = fmaxf(fmaf(inv, v.x, bb), 0.f);
                u1 = fmaxf(fmaf(inv, v.y, bb), 0.f);
                if (left) uL = fmaxf(fmaf(inv, rp[-1], bb), 0.f);
            }
            const float* wp = &sw[ic*9 + r*3];
            a0 = fmaf(wp[0],  uL, fmaf(wp[1],  u0, fmaf(wp[2],  u1, a0)));
            a1 = fmaf(wp[27], uL, fmaf(wp[28], u0, fmaf(wp[29], u1, a1)));
            a2 = fmaf(wp[54], uL, fmaf(wp[55], u0, fmaf(wp[56], u1, a2)));
        }
    }
    outp[((b*3 + 0)*OUTW + oy)*OUTW + ox] = a0;
    outp[((b*3 + 1)*OUTW + oy)*OUTW + ox] = a1;
    outp[((b*3 + 2)*OUTW + oy)*OUTW + ox] = a2;
}

template<int STAGE>
__global__ void k_ctxp(const float* __restrict__ w,
                       const float* __restrict__ bias,
                       const float* __restrict__ bng,
                       const float* __restrict__ bnb) {
    __shared__ float sw[81], sb[3], sinv[3], sbb[3];
    for (int t = threadIdx.x; t < 81; t += blockDim.x) sw[t] = w[t];
    if (threadIdx.x < 3) {
        sb[threadIdx.x]   = bias[threadIdx.x];
        sinv[threadIdx.x] = bng[threadIdx.x] * rsqrtf(1.001f);
        sbb[threadIdx.x]  = bnb[threadIdx.x];
    }
    __syncthreads();
    int i = blockIdx.x*blockDim.x + threadIdx.x;
    ctx_px_body<STAGE>(i, sw, sb, sinv, sbb);
}

// ---------------- mid: role-split kernel. Blocks [0,128): pools; [128,640): ctx2 ----------------
__global__ void k_mid(const float* __restrict__ samw, const float* __restrict__ samb,
                      const float* __restrict__ w1, const float* __restrict__ b1,
                      const float* __restrict__ w2, const float* __restrict__ b2,
                      const float* __restrict__ cw, const float* __restrict__ cb,
                      const float* __restrict__ bng, const float* __restrict__ bnb) {
    int tid = threadIdx.x;
    if (blockIdx.x < 128) {
        // ---- pool role: inv_sigma (float closed form) + pool1 + pool2 ----
        __shared__ float sG[9];
        __shared__ float sis;
        __shared__ float sw1[36], sw2[36], sb1[3], sb2[3], sbs[3];
        if (tid < 36) { sw1[tid] = w1[tid]; sw2[tid] = w2[tid]; }
        if (tid >= 64 && tid < 67) {
            int c = tid - 64;
            sb1[c] = b1[c]; sb2[c] = b2[c]; sbs[c] = samb[c];
        }
        if (tid >= 96 && tid < 105) {
            int t9 = tid - 96;
            int ii = t9 / 3, jj = t9 % 3;
            float s0 = 0.f, s1 = 0.f, s2 = 0.f, s3 = 0.f;
            #pragma unroll
            for (int k = 0; k < 48; k += 4) {
                s0 += samw[ii*48 + k + 0] * samw[jj*48 + k + 0];
                s1 += samw[ii*48 + k + 1] * samw[jj*48 + k + 1];
                s2 += samw[ii*48 + k + 2] * samw[jj*48 + k + 2];
                s3 += samw[ii*48 + k + 3] * samw[jj*48 + k + 3];
            }
            sG[t9] = (s0 + s1) + (s2 + s3);
        }
        __syncthreads();
        if (tid == 0) {
            float g00 = sG[0], g01 = sG[1], g02 = sG[2];
            float g11 = sG[4], g12 = sG[5], g22 = sG[8];
            float q  = (g00 + g11 + g22) * (1.f/3.f);
            float pp = g01*g01 + g02*g02 + g12*g12;
            float d0 = g00 - q, d1 = g11 - q, d2 = g22 - q;
            float p2 = d0*d0 + d1*d1 + d2*d2 + 2.f*pp;
            float lam;
            if (p2 <= 1e-30f) {
                lam = q;
            } else {
                float p  = sqrtf(p2 * (1.f/6.f));
                float ip = 1.f/p;
                float b00 = d0*ip, b11 = d1*ip, b22 = d2*ip;
                float b01 = g01*ip, b02 = g02*ip, b12 = g12*ip;
                float detB = b00*(b11*b22 - b12*b12)
                           - b01*(b01*b22 - b12*b02)
                           + b02*(b01*b12 - b11*b02);
                float r = fminf(1.f, fmaxf(-1.f, 0.5f*detB));
                lam = q + 2.f*p*cosf(acosf(r)*(1.f/3.f));
            }
            float is = rsqrtf(lam);
            sis = is;
            if (blockIdx.x == 0) g_inv_sigma = is;
        }
        __syncthreads();
        float is = sis;

        int i  = blockIdx.x*256 + tid;
        int ox = i & 63;
        int oy = (i >> 6) & 63;
        int b  = i >> 12;

        float p1v[2][2][3];
        #pragma unroll
        for (int sy = 0; sy < 2; sy++)
            #pragma unroll
            for (int sx = 0; sx < 2; sx++)
                #pragma unroll
                for (int mc = 0; mc < 3; mc++)
                    p1v[sy][sx][mc] = sb1[mc];

        #pragma unroll
        for (int ic = 0; ic < 3; ic++) {
            const float* base = g_x + (size_t)(b*3 + ic)*65536 + (size_t)(4*oy)*256 + 4*ox;
            float bsc = sbs[ic];
            float rx[4][4];
            #pragma unroll
            for (int r = 0; r < 4; r++) {
                float4 v = *reinterpret_cast<const float4*>(base + r*256);
                rx[r][0] = fmaf(v.x, is, bsc);
                rx[r][1] = fmaf(v.y, is, bsc);
                rx[r][2] = fmaf(v.z, is, bsc);
                rx[r][3] = fmaf(v.w, is, bsc);
            }
            #pragma unroll
            for (int mc = 0; mc < 3; mc++) {
                const float* wp = &sw1[mc*12 + ic*4];
                #pragma unroll
                for (int sy = 0; sy < 2; sy++)
                    #pragma unroll
                    for (int sx = 0; sx < 2; sx++)
                        p1v[sy][sx][mc] += wp[0]*rx[2*sy][2*sx]   + wp[1]*rx[2*sy][2*sx+1]
                                         + wp[2]*rx[2*sy+1][2*sx] + wp[3]*rx[2*sy+1][2*sx+1];
            }
        }

        #pragma unroll
        for (int mc = 0; mc < 3; mc++)
            #pragma unroll
            for (int sy = 0; sy < 2; sy++) {
                size_t o = ((size_t)(b*3 + mc)*128 + 2*oy + sy)*128 + 2*ox;
                *reinterpret_cast<float2*>(g_p1 + o) = make_float2(p1v[sy][0][mc], p1v[sy][1][mc]);
            }

        #pragma unroll
        for (int oc = 0; oc < 3; oc++) {
            float a = sb2[oc];
            #pragma unroll
            for (int mc = 0; mc < 3; mc++) {
                const float* wp = &sw2[oc*12 + mc*4];
                a += wp[0]*p1v[0][0][mc] + wp[1]*p1v[0][1][mc]
                   + wp[2]*p1v[1][0][mc] + wp[3]*p1v[1][1][mc];
            }
            g_p2[((size_t)(b*3 + oc)*64 + oy)*64 + ox] = a;
        }
    } else {
        // ---- ctx2 role ----
        __shared__ float sw[81], sb[3], sinv[3], sbb[3];
        for (int t = tid; t < 81; t += 256) sw[t] = cw[t];
        if (tid < 3) {
            sb[tid]   = cb[tid];
            sinv[tid] = bng[tid] * rsqrtf(1.001f);
            sbb[tid]  = bnb[tid];
        }
        __syncthreads();
        int i = (blockIdx.x - 128)*256 + tid;
        ctx_px_body<2>(i, sw, sb, sinv, sbb);
    }
}

// ---------------- mega: soft-VQ main (2 px/thread) + mask1 + mask2 + finalize ----------------
__global__ void k_mega(const float* __restrict__ thresh,
                       const float* __restrict__ centers,
                       const float* __restrict__ samb,
                       float* __restrict__ out, int soft_n) {
    __shared__ float sc[8];
    __shared__ unsigned int shist[8];
    __shared__ unsigned int sesti;
    __shared__ float sth[2];
    __shared__ float sbs[3];
    __shared__ float s_is;
    int tid = threadIdx.x;
    if (tid < 8) { sc[tid] = centers[tid]; shist[tid] = 0u; }
    if (tid < 2) sth[tid] = thresh[tid];
    if (tid < 3) sbs[tid] = samb[tid];
    if (tid == 0) { sesti = 0u; s_is = g_inv_sigma; }
    __syncthreads();

    int t = blockIdx.x*blockDim.x + tid;     // 0 .. 786431
    unsigned int ev;
    float is = s_is;

    // ---- main part: pixels 2t, 2t+1 ----
    {
        int i = 2*t;
        int xp = i & 255, y = (i >> 8) & 255, bc = i >> 16;
        int c = bc % 3;
        float2 tv = *reinterpret_cast<const float2*>(g_x + i);
        float x0 = fmaf(tv.x, is, sbs[c]);
        float x1 = fmaf(tv.y, is, sbs[c]);
        int hi = bc*16384 + (y >> 1)*128 + (xp >> 1);
        int qi = bc*4096  + (y >> 2)*64  + (xp >> 2);
        float f1 = 0.5f*(tanhf(g_h2[hi]) + 1.0f);
        float f2 = 0.5f*(tanhf(g_h3[qi]) + 1.0f);
        bool c2 = f2 < sth[1];
        bool c1 = (!c2) && (f1 < sth[0]);
        bool c0 = !(c1 || c2);
        float rep = c1 ? g_p1[hi] : (c2 ? g_p2[qi] : 0.f);
        float xq0 = c0 ? x0 : rep;
        float xq1 = c0 ? x1 : rep;

        float r0, r1;
        int imin0 = 0, imin1 = 0;
        {
            float dd[8]; float dmin = 3.4e38f;
            #pragma unroll
            for (int k = 0; k < 8; k++) {
                float d = (xq0 - sc[k])*(xq0 - sc[k]);
                dd[k] = d;
                if (d < dmin) { dmin = d; imin0 = k; }
            }
            float s = 0.f, sn = 0.f;
            #pragma unroll
            for (int k = 0; k < 8; k++) {
                float e = __expf(dmin - dd[k]);
                s += e; sn = fmaf(e, sc[k], sn);
            }
            r0 = sn / s;
        }
        {
            float dd[8]; float dmin = 3.4e38f;
            #pragma unroll
            for (int k = 0; k < 8; k++) {
                float d = (xq1 - sc[k])*(xq1 - sc[k]);
                dd[k] = d;
                if (d < dmin) { dmin = d; imin1 = k; }
            }
            float s = 0.f, sn = 0.f;
            #pragma unroll
            for (int k = 0; k < 8; k++) {
                float e = __expf(dmin - dd[k]);
                s += e; sn = fmaf(e, sc[k], sn);
            }
            r1 = sn / s;
        }
        *reinterpret_cast<float2*>(out + i) = make_float2(r0, r1);

        ev = 2u * (c0 ? 16u : (c1 ? 4u : 1u));
        if (c0) {
            atomicAdd(&shist[imin0], 1u);
            atomicAdd(&shist[imin1], 1u);
        }
    }

    // ---- mask1 part ----
    if (t < NB*NC*128*128) {
        int xp = t & 127, y = (t >> 7) & 127, bc = t >> 14;
        float f1 = 0.5f*(tanhf(g_h2[t]) + 1.0f);
        float f2 = 0.5f*(tanhf(g_h3[bc*4096 + (y >> 1)*64 + (xp >> 1)]) + 1.0f);
        if (f2 >= sth[1] && f1 < sth[0]) {
            float p = g_p1[t];
            float dmin = 3.4e38f; int imin = 0;
            #pragma unroll
            for (int k = 0; k < 8; k++) {
                float d = (p - sc[k])*(p - sc[k]);
                if (d < dmin) { dmin = d; imin = k; }
            }
            atomicAdd(&shist[imin], 1u);
        }
    }

    // ---- mask2 part ----
    if (t < NB*NC*64*64) {
        float f2 = 0.5f*(tanhf(g_h3[t]) + 1.0f);
        if (f2 < sth[1]) {
            float p = g_p2[t];
            float dmin = 3.4e38f; int imin = 0;
            #pragma unroll
            for (int k = 0; k < 8; k++) {
                float d = (p - sc[k])*(p - sc[k]);
                if (d < dmin) { dmin = d; imin = k; }
            }
            atomicAdd(&shist[imin], 1u);
        }
    }

    // ---- block reductions + flush ----
    unsigned int wsum = __reduce_add_sync(0xffffffffu, ev);
    if ((tid & 31) == 0) atomicAdd(&sesti, wsum);
    __syncthreads();
    if (tid < 8) {
        if (shist[tid]) atomicAdd(&g_counts[tid], shist[tid]);
        if (tid == 0) atomicAdd(&g_esti16, sesti);
        __threadfence();
    }
    __syncthreads();

    // ---- last-block finalize (then reset accumulators for next replay) ----
    if (tid == 0) {
        unsigned int ticket = atomicAdd(&g_done, 1u);
        if (ticket == gridDim.x - 1) {
            double tot = 0.0;
            double c[8];
            for (int k = 0; k < 8; k++) {
                c[k] = (double)atomicAdd(&g_counts[k], 0u);
                tot += c[k];
            }
            double mean = 0.0;
            for (int k = 0; k < 8; k++) { c[k] /= tot; mean += c[k]; }
            mean /= 8.0;
            double var = 0.0;
            for (int k = 0; k < 8; k++) { double d = c[k] - mean; var += d*d; }
            double stdv = sqrt(var / 7.0);
            double esti = (double)atomicAdd(&g_esti16, 0u) / 16.0;
            double cr = (1.0/16.0) * esti / (256.0*256.0*3.0*8.0);
            out[soft_n]     = (float)cr;
            out[soft_n + 1] = (float)stdv;
            for (int k = 0; k < 8; k++) g_counts[k] = 0u;
            g_esti16 = 0u;
            __threadfence();
            atomicExch(&g_done, 0u);
        }
    }
}

// ---------------- launch ----------------
extern "C" void kernel_launch(void* const* d_in, const int* in_sizes, int n_in,
                              void* d_out, int out_size) {
    const float* x_init   = (const float*)d_in[0];
    const float* thresh   = (const float*)d_in[1];
    const float* sample_w = (const float*)d_in[2];
    const float* sample_b = (const float*)d_in[3];
    const float* centers  = (const float*)d_in[4];
    const float* pool1_w  = (const float*)d_in[5];
    const float* pool1_b  = (const float*)d_in[6];
    const float* pool2_w  = (const float*)d_in[7];
    const float* pool2_b  = (const float*)d_in[8];
    const float* ctx_w    = (const float*)d_in[9];
    const float* ctx_b    = (const float*)d_in[10];
    const float* bng      = (const float*)d_in[11];
    const float* bnb      = (const float*)d_in[12];
    float* out = (float*)d_out;
    int soft_n = out_size - 2;

    k_fused<<<dim3(256, 8), 256>>>(x_init, sample_w,
                                   ctx_w + 0*81, ctx_b + 0*3, bng + 0*3, bnb + 0*3);
    k_ctxp<1><<<2048, 256>>>(ctx_w + 1*81, ctx_b + 1*3, bng + 1*3, bnb + 1*3);
    k_mid<<<640, 256>>>(sample_w, sample_b,
                        pool1_w, pool1_b, pool2_w, pool2_b,
                        ctx_w + 2*81, ctx_b + 2*3, bng + 2*3, bnb + 2*3);
    k_ctxp<3><<<128, 256>>>(ctx_w + 3*81, ctx_b + 3*3, bng + 3*3, bnb + 3*3);
    k_mega<<<3072, 256>>>(thresh, centers, sample_b, out, soft_n);
}

// round 8
// speedup vs baseline: 1.8795x; 1.0056x over previous
#include <cuda_runtime.h>
#include <math.h>

#define NB 8
#define NC 3

// ---------------- scratch (device globals; no runtime allocation) ----------------
__device__ float g_x [NB*NC*256*256];   // UNSCALED sample conv output (no sigma, no bias)
__device__ float g_h0[NB*NC*512*512];
__device__ float g_h1[NB*NC*256*256];
__device__ float g_h2[NB*NC*128*128];
__device__ float g_h3[NB*NC*64*64];
__device__ float g_p1[NB*NC*128*128];
__device__ float g_p2[NB*NC*64*64];
__device__ float g_inv_sigma;
__device__ unsigned int g_counts[8];    // zero-init at load; reset by mega finalize
__device__ unsigned int g_esti16;
__device__ unsigned int g_done = 0;
__device__ unsigned int g_bar_cnt = 0;  // grid barrier (sense-reversing)
__device__ unsigned int g_bar_sense = 0;

// ---------------- fused: sample conv (4x4 s4, unscaled) + ctx stage 0 ----------------
__global__ void k_fused(const float* __restrict__ x,
                        const float* __restrict__ samw,
                        const float* __restrict__ cw,
                        const float* __restrict__ cb,
                        const float* __restrict__ bng,
                        const float* __restrict__ bnb) {
    __shared__ float ssw[144];
    __shared__ float scw[81], scb[3], sinv[3], sbb[3];
    int tid = threadIdx.x;
    if (tid < 144) ssw[tid] = samw[tid];
    if (tid < 81)  scw[tid] = cw[tid];
    if (tid < 3) {
        scb[tid]  = cb[tid];
        sinv[tid] = bng[tid] * rsqrtf(1.001f);
        sbb[tid]  = bnb[tid];
    }
    __syncthreads();

    int ox = threadIdx.x;
    int oy = blockIdx.x;
    int b  = blockIdx.y;

    float as0 = 0.f, as1 = 0.f, as2 = 0.f;
    float ac[2][2][3];
    #pragma unroll
    for (int sy = 0; sy < 2; sy++)
        #pragma unroll
        for (int sx = 0; sx < 2; sx++)
            #pragma unroll
            for (int oc = 0; oc < 3; oc++)
                ac[sy][sx][oc] = scb[oc];

    bool left = (ox > 0);

    #pragma unroll
    for (int ic = 0; ic < 3; ic++) {
        const float* base = x + (size_t)(b*3 + ic)*1024*1024;
        float inv = sinv[ic], bb = sbb[ic];
        #pragma unroll
        for (int r5 = 0; r5 < 5; r5++) {
            int iy = 4*oy + r5 - 1;
            float u0, u1, u2, u3, u4;
            if (iy >= 0) {
                const float* rp = base + (size_t)iy*1024 + 4*ox;
                float4 v4 = *reinterpret_cast<const float4*>(rp);
                float vm = left ? rp[-1] : 0.f;
                u0 = left ? fmaxf(fmaf(inv, vm, bb), 0.f) : 0.f;
                u1 = fmaxf(fmaf(inv, v4.x, bb), 0.f);
                u2 = fmaxf(fmaf(inv, v4.y, bb), 0.f);
                u3 = fmaxf(fmaf(inv, v4.z, bb), 0.f);
                u4 = fmaxf(fmaf(inv, v4.w, bb), 0.f);
                if (r5 >= 1) {
                    int ky = r5 - 1;
                    const float* w0 = &ssw[(0*3 + ic)*16 + ky*4];
                    const float* w1 = &ssw[(1*3 + ic)*16 + ky*4];
                    const float* w2 = &ssw[(2*3 + ic)*16 + ky*4];
                    as0 += w0[0]*v4.x + w0[1]*v4.y + w0[2]*v4.z + w0[3]*v4.w;
                    as1 += w1[0]*v4.x + w1[1]*v4.y + w1[2]*v4.z + w1[3]*v4.w;
                    as2 += w2[0]*v4.x + w2[1]*v4.y + w2[2]*v4.z + w2[3]*v4.w;
                }
            } else {
                u0 = u1 = u2 = u3 = u4 = 0.f;
            }
            if (r5 <= 2) {
                #pragma unroll
                for (int oc = 0; oc < 3; oc++) {
                    const float* wp = &scw[oc*27 + ic*9 + r5*3];
                    ac[0][0][oc] = fmaf(wp[0], u0, fmaf(wp[1], u1, fmaf(wp[2], u2, ac[0][0][oc])));
                    ac[0][1][oc] = fmaf(wp[0], u2, fmaf(wp[1], u3, fmaf(wp[2], u4, ac[0][1][oc])));
                }
            }
            if (r5 >= 2) {
                int ky = r5 - 2;
                #pragma unroll
                for (int oc = 0; oc < 3; oc++) {
                    const float* wp = &scw[oc*27 + ic*9 + ky*3];
                    ac[1][0][oc] = fmaf(wp[0], u0, fmaf(wp[1], u1, fmaf(wp[2], u2, ac[1][0][oc])));
                    ac[1][1][oc] = fmaf(wp[0], u2, fmaf(wp[1], u3, fmaf(wp[2], u4, ac[1][1][oc])));
                }
            }
        }
    }

    g_x[((b*3 + 0)*256 + oy)*256 + ox] = as0;
    g_x[((b*3 + 1)*256 + oy)*256 + ox] = as1;
    g_x[((b*3 + 2)*256 + oy)*256 + ox] = as2;

    #pragma unroll
    for (int oc = 0; oc < 3; oc++) {
        #pragma unroll
        for (int sy = 0; sy < 2; sy++) {
            size_t o = ((size_t)(b*3 + oc)*512 + 2*oy + sy)*512 + 2*ox;
            *reinterpret_cast<float2*>(g_h0 + o) = make_float2(ac[sy][0][oc], ac[sy][1][oc]);
        }
    }
}

// ---------------- per-pixel ctx conv body (stages 1..3) ----------------
template<int STAGE>
__device__ __forceinline__ void ctx_px_body(int i,
                                            const float* sw, const float* sb,
                                            const float* sinv, const float* sbb) {
    constexpr int INH  = (STAGE == 1) ? 512 : (STAGE == 2) ? 256 : 128;
    constexpr int OUTW = INH / 2;
    constexpr int LOG  = (STAGE == 1) ? 8 : (STAGE == 2) ? 7 : 6;
    const float* in = (STAGE == 1) ? g_h0 : (STAGE == 2) ? g_h1 : g_h2;
    float* outp     = (STAGE == 1) ? g_h1 : (STAGE == 2) ? g_h2 : g_h3;

    int ox = i & (OUTW - 1);
    int oy = (i >> LOG) & (OUTW - 1);
    int b  = i >> (2*LOG);

    float a0 = sb[0], a1 = sb[1], a2 = sb[2];
    bool left = (ox > 0);
    #pragma unroll
    for (int ic = 0; ic < 3; ic++) {
        const float* base = in + (size_t)(b*3 + ic)*INH*INH;
        float inv = sinv[ic], bb = sbb[ic];
        #pragma unroll
        for (int r = 0; r < 3; r++) {
            int iy = 2*oy + r - 1;
            float uL = 0.f, u0 = 0.f, u1 = 0.f;
            if (iy >= 0) {
                const float* rp = base + (size_t)iy*INH + 2*ox;
                float2 v = *reinterpret_cast<const float2*>(rp);
                u0 = fmaxf(fmaf(inv, v.x, bb), 0.f);
                u1 = fmaxf(fmaf(inv, v.y, bb), 0.f);
                if (left) uL = fmaxf(fmaf(inv, rp[-1], bb), 0.f);
            }
            const float* wp = &sw[ic*9 + r*3];
            a0 = fmaf(wp[0],  uL, fmaf(wp[1],  u0, fmaf(wp[2],  u1, a0)));
            a1 = fmaf(wp[27], uL, fmaf(wp[28], u0, fmaf(wp[29], u1, a1)));
            a2 = fmaf(wp[54], uL, fmaf(wp[55], u0, fmaf(wp[56], u1, a2)));
        }
    }
    outp[((b*3 + 0)*OUTW + oy)*OUTW + ox] = a0;
    outp[((b*3 + 1)*OUTW + oy)*OUTW + ox] = a1;
    outp[((b*3 + 2)*OUTW + oy)*OUTW + ox] = a2;
}

// ---------------- role-split: ctx1 (blocks [0,2048)) + pools (blocks [2048,2176)) ----------------
__global__ void k_ctx1pool(const float* __restrict__ w1c, const float* __restrict__ b1c,
                           const float* __restrict__ bng1, const float* __restrict__ bnb1,
                           const float* __restrict__ samw, const float* __restrict__ samb,
                           const float* __restrict__ pw1, const float* __restrict__ pb1,
                           const float* __restrict__ pw2, const float* __restrict__ pb2) {
    int tid = threadIdx.x;
    if (blockIdx.x < 2048) {
        // ---- ctx1 role ----
        __shared__ float sw[81], sb[3], sinv[3], sbb[3];
        for (int t = tid; t < 81; t += 256) sw[t] = w1c[t];
        if (tid < 3) {
            sb[tid]   = b1c[tid];
            sinv[tid] = bng1[tid] * rsqrtf(1.001f);
            sbb[tid]  = bnb1[tid];
        }
        __syncthreads();
        int i = blockIdx.x*256 + tid;
        ctx_px_body<1>(i, sw, sb, sinv, sbb);
    } else {
        // ---- pool role: inv_sigma (float closed form) + pool1 + pool2 ----
        __shared__ float sG[9];
        __shared__ float sis;
        __shared__ float sw1[36], sw2[36], sb1[3], sb2[3], sbs[3];
        if (tid < 36) { sw1[tid] = pw1[tid]; sw2[tid] = pw2[tid]; }
        if (tid >= 64 && tid < 67) {
            int c = tid - 64;
            sb1[c] = pb1[c]; sb2[c] = pb2[c]; sbs[c] = samb[c];
        }
        if (tid >= 96 && tid < 105) {
            int t9 = tid - 96;
            int ii = t9 / 3, jj = t9 % 3;
            float s0 = 0.f, s1 = 0.f, s2 = 0.f, s3 = 0.f;
            #pragma unroll
            for (int k = 0; k < 48; k += 4) {
                s0 += samw[ii*48 + k + 0] * samw[jj*48 + k + 0];
                s1 += samw[ii*48 + k + 1] * samw[jj*48 + k + 1];
                s2 += samw[ii*48 + k + 2] * samw[jj*48 + k + 2];
                s3 += samw[ii*48 + k + 3] * samw[jj*48 + k + 3];
            }
            sG[t9] = (s0 + s1) + (s2 + s3);
        }
        __syncthreads();
        if (tid == 0) {
            float g00 = sG[0], g01 = sG[1], g02 = sG[2];
            float g11 = sG[4], g12 = sG[5], g22 = sG[8];
            float q  = (g00 + g11 + g22) * (1.f/3.f);
            float pp = g01*g01 + g02*g02 + g12*g12;
            float d0 = g00 - q, d1 = g11 - q, d2 = g22 - q;
            float p2 = d0*d0 + d1*d1 + d2*d2 + 2.f*pp;
            float lam;
            if (p2 <= 1e-30f) {
                lam = q;
            } else {
                float p  = sqrtf(p2 * (1.f/6.f));
                float ip = 1.f/p;
                float b00 = d0*ip, b11 = d1*ip, b22 = d2*ip;
                float b01 = g01*ip, b02 = g02*ip, b12 = g12*ip;
                float detB = b00*(b11*b22 - b12*b12)
                           - b01*(b01*b22 - b12*b02)
                           + b02*(b01*b12 - b11*b02);
                float r = fminf(1.f, fmaxf(-1.f, 0.5f*detB));
                lam = q + 2.f*p*cosf(acosf(r)*(1.f/3.f));
            }
            float is = rsqrtf(lam);
            sis = is;
            if (blockIdx.x == 2048) g_inv_sigma = is;
        }
        __syncthreads();
        float is = sis;

        int i  = (blockIdx.x - 2048)*256 + tid;
        int ox = i & 63;
        int oy = (i >> 6) & 63;
        int b  = i >> 12;

        float p1v[2][2][3];
        #pragma unroll
        for (int sy = 0; sy < 2; sy++)
            #pragma unroll
            for (int sx = 0; sx < 2; sx++)
                #pragma unroll
                for (int mc = 0; mc < 3; mc++)
                    p1v[sy][sx][mc] = sb1[mc];

        #pragma unroll
        for (int ic = 0; ic < 3; ic++) {
            const float* base = g_x + (size_t)(b*3 + ic)*65536 + (size_t)(4*oy)*256 + 4*ox;
            float bsc = sbs[ic];
            float rx[4][4];
            #pragma unroll
            for (int r = 0; r < 4; r++) {
                float4 v = *reinterpret_cast<const float4*>(base + r*256);
                rx[r][0] = fmaf(v.x, is, bsc);
                rx[r][1] = fmaf(v.y, is, bsc);
                rx[r][2] = fmaf(v.z, is, bsc);
                rx[r][3] = fmaf(v.w, is, bsc);
            }
            #pragma unroll
            for (int mc = 0; mc < 3; mc++) {
                const float* wp = &sw1[mc*12 + ic*4];
                #pragma unroll
                for (int sy = 0; sy < 2; sy++)
                    #pragma unroll
                    for (int sx = 0; sx < 2; sx++)
                        p1v[sy][sx][mc] += wp[0]*rx[2*sy][2*sx]   + wp[1]*rx[2*sy][2*sx+1]
                                         + wp[2]*rx[2*sy+1][2*sx] + wp[3]*rx[2*sy+1][2*sx+1];
            }
        }

        #pragma unroll
        for (int mc = 0; mc < 3; mc++)
            #pragma unroll
            for (int sy = 0; sy < 2; sy++) {
                size_t o = ((size_t)(b*3 + mc)*128 + 2*oy + sy)*128 + 2*ox;
                *reinterpret_cast<float2*>(g_p1 + o) = make_float2(p1v[sy][0][mc], p1v[sy][1][mc]);
            }

        #pragma unroll
        for (int oc = 0; oc < 3; oc++) {
            float a = sb2[oc];
            #pragma unroll
            for (int mc = 0; mc < 3; mc++) {
                const float* wp = &sw2[oc*12 + mc*4];
                a += wp[0]*p1v[0][0][mc] + wp[1]*p1v[0][1][mc]
                   + wp[2]*p1v[1][0][mc] + wp[3]*p1v[1][1][mc];
            }
            g_p2[((size_t)(b*3 + oc)*64 + oy)*64 + ox] = a;
        }
    }
}

// ---------------- ctx2 + ctx3 in one kernel with a co-resident grid barrier ----------------
// Grid: 512 blocks x 256 threads, __launch_bounds__(256, 4) -> 4 blocks/SM x 148 SMs = 592
// co-resident slots >= 512 blocks, so the sense-reversing spin barrier cannot deadlock.
__global__ void __launch_bounds__(256, 4)
k_tail23(const float* __restrict__ w2c, const float* __restrict__ b2c,
         const float* __restrict__ bng2, const float* __restrict__ bnb2,
         const float* __restrict__ w3c, const float* __restrict__ b3c,
         const float* __restrict__ bng3, const float* __restrict__ bnb3) {
    __shared__ float sw2[81], sb2[3], sinv2[3], sbb2[3];
    __shared__ float sw3[81], sb3[3], sinv3[3], sbb3[3];
    int tid = threadIdx.x;
    for (int t = tid; t < 81; t += 256) { sw2[t] = w2c[t]; sw3[t] = w3c[t]; }
    if (tid < 3) {
        sb2[tid]   = b2c[tid];
        sinv2[tid] = bng2[tid] * rsqrtf(1.001f);
        sbb2[tid]  = bnb2[tid];
        sb3[tid]   = b3c[tid];
        sinv3[tid] = bng3[tid] * rsqrtf(1.001f);
        sbb3[tid]  = bnb3[tid];
    }
    __syncthreads();

    // ---- phase 1: ctx2 (exactly 512*256 = 131072 = NB*128*128 outputs) ----
    int i = blockIdx.x*256 + tid;
    ctx_px_body<2>(i, sw2, sb2, sinv2, sbb2);

    // ---- grid barrier (sense-reversing) ----
    __threadfence();
    __syncthreads();
    if (tid == 0) {
        unsigned int S = *(volatile unsigned int*)&g_bar_sense;
        unsigned int a = atomicAdd(&g_bar_cnt, 1u);
        if (a == gridDim.x - 1u) {
            g_bar_cnt = 0u;
            __threadfence();
            atomicExch(&g_bar_sense, S ^ 1u);
        } else {
            while (*(volatile unsigned int*)&g_bar_sense == S) { }
        }
    }
    __syncthreads();

    // ---- phase 2: ctx3 (first 32768 threads = NB*64*64 outputs) ----
    if (i < NB*64*64) {
        ctx_px_body<3>(i, sw3, sb3, sinv3, sbb3);
    }
}

// ---------------- mega: soft-VQ main (2 px/thread) + mask1 + mask2 + finalize ----------------
__global__ void k_mega(const float* __restrict__ thresh,
                       const float* __restrict__ centers,
                       const float* __restrict__ samb,
                       float* __restrict__ out, int soft_n) {
    __shared__ float sc[8];
    __shared__ unsigned int shist[8];
    __shared__ unsigned int sesti;
    __shared__ float sth[2];
    __shared__ float sbs[3];
    __shared__ float s_is;
    int tid = threadIdx.x;
    if (tid < 8) { sc[tid] = centers[tid]; shist[tid] = 0u; }
    if (tid < 2) sth[tid] = thresh[tid];
    if (tid < 3) sbs[tid] = samb[tid];
    if (tid == 0) { sesti = 0u; s_is = g_inv_sigma; }
    __syncthreads();

    int t = blockIdx.x*blockDim.x + tid;
    unsigned int ev;
    float is = s_is;

    {
        int i = 2*t;
        int xp = i & 255, y = (i >> 8) & 255, bc = i >> 16;
        int c = bc % 3;
        float2 tv = *reinterpret_cast<const float2*>(g_x + i);
        float x0 = fmaf(tv.x, is, sbs[c]);
        float x1 = fmaf(tv.y, is, sbs[c]);
        int hi = bc*16384 + (y >> 1)*128 + (xp >> 1);
        int qi = bc*4096  + (y >> 2)*64  + (xp >> 2);
        float f1 = 0.5f*(tanhf(g_h2[hi]) + 1.0f);
        float f2 = 0.5f*(tanhf(g_h3[qi]) + 1.0f);
        bool c2 = f2 < sth[1];
        bool c1 = (!c2) && (f1 < sth[0]);
        bool c0 = !(c1 || c2);
        float rep = c1 ? g_p1[hi] : (c2 ? g_p2[qi] : 0.f);
        float xq0 = c0 ? x0 : rep;
        float xq1 = c0 ? x1 : rep;

        float r0, r1;
        int imin0 = 0, imin1 = 0;
        {
            float dd[8]; float dmin = 3.4e38f;
            #pragma unroll
            for (int k = 0; k < 8; k++) {
                float d = (xq0 - sc[k])*(xq0 - sc[k]);
                dd[k] = d;
                if (d < dmin) { dmin = d; imin0 = k; }
            }
            float s = 0.f, sn = 0.f;
            #pragma unroll
            for (int k = 0; k < 8; k++) {
                float e = __expf(dmin - dd[k]);
                s += e; sn = fmaf(e, sc[k], sn);
            }
            r0 = sn / s;
        }
        {
            float dd[8]; float dmin = 3.4e38f;
            #pragma unroll
            for (int k = 0; k < 8; k++) {
                float d = (xq1 - sc[k])*(xq1 - sc[k]);
                dd[k] = d;
                if (d < dmin) { dmin = d; imin1 = k; }
            }
            float s = 0.f, sn = 0.f;
            #pragma unroll
            for (int k = 0; k < 8; k++) {
                float e = __expf(dmin - dd[k]);
                s += e; sn = fmaf(e, sc[k], sn);
            }
            r1 = sn / s;
        }
        *reinterpret_cast<float2*>(out + i) = make_float2(r0, r1);

        ev = 2u * (c0 ? 16u : (c1 ? 4u : 1u));
        if (c0) {
            atomicAdd(&shist[imin0], 1u);
            atomicAdd(&shist[imin1], 1u);
        }
    }

    if (t < NB*NC*128*128) {
        int xp = t & 127, y = (t >> 7) & 127, bc = t >> 14;
        float f1 = 0.5f*(tanhf(g_h2[t]) + 1.0f);
        float f2 = 0.5f*(tanhf(g_h3[bc*4096 + (y >> 1)*64 + (xp >> 1)]) + 1.0f);
        if (f2 >= sth[1] && f1 < sth[0]) {
            float p = g_p1[t];
            float dmin = 3.4e38f; int imin = 0;
            #pragma unroll
            for (int k = 0; k < 8; k++) {
                float d = (p - sc[k])*(p - sc[k]);
                if (d < dmin) { dmin = d; imin = k; }
            }
            atomicAdd(&shist[imin], 1u);
        }
    }

    if (t < NB*NC*64*64) {
        float f2 = 0.5f*(tanhf(g_h3[t]) + 1.0f);
        if (f2 < sth[1]) {
            float p = g_p2[t];
            float dmin = 3.4e38f; int imin = 0;
            #pragma unroll
            for (int k = 0; k < 8; k++) {
                float d = (p - sc[k])*(p - sc[k]);
                if (d < dmin) { dmin = d; imin = k; }
            }
            atomicAdd(&shist[imin], 1u);
        }
    }

    unsigned int wsum = __reduce_add_sync(0xffffffffu, ev);
    if ((tid & 31) == 0) atomicAdd(&sesti, wsum);
    __syncthreads();
    if (tid < 8) {
        if (shist[tid]) atomicAdd(&g_counts[tid], shist[tid]);
        if (tid == 0) atomicAdd(&g_esti16, sesti);
        __threadfence();
    }
    __syncthreads();

    if (tid == 0) {
        unsigned int ticket = atomicAdd(&g_done, 1u);
        if (ticket == gridDim.x - 1) {
            double tot = 0.0;
            double c[8];
            for (int k = 0; k < 8; k++) {
                c[k] = (double)atomicAdd(&g_counts[k], 0u);
                tot += c[k];
            }
            double mean = 0.0;
            for (int k = 0; k < 8; k++) { c[k] /= tot; mean += c[k]; }
            mean /= 8.0;
            double var = 0.0;
            for (int k = 0; k < 8; k++) { double d = c[k] - mean; var += d*d; }
            double stdv = sqrt(var / 7.0);
            double esti = (double)atomicAdd(&g_esti16, 0u) / 16.0;
            double cr = (1.0/16.0) * esti / (256.0*256.0*3.0*8.0);
            out[soft_n]     = (float)cr;
            out[soft_n + 1] = (float)stdv;
            for (int k = 0; k < 8; k++) g_counts[k] = 0u;
            g_esti16 = 0u;
            __threadfence();
            atomicExch(&g_done, 0u);
        }
    }
}

// ---------------- launch ----------------
extern "C" void kernel_launch(void* const* d_in, const int* in_sizes, int n_in,
                              void* d_out, int out_size) {
    const float* x_init   = (const float*)d_in[0];
    const float* thresh   = (const float*)d_in[1];
    const float* sample_w = (const float*)d_in[2];
    const float* sample_b = (const float*)d_in[3];
    const float* centers  = (const float*)d_in[4];
    const float* pool1_w  = (const float*)d_in[5];
    const float* pool1_b  = (const float*)d_in[6];
    const float* pool2_w  = (const float*)d_in[7];
    const float* pool2_b  = (const float*)d_in[8];
    const float* ctx_w    = (const float*)d_in[9];
    const float* ctx_b    = (const float*)d_in[10];
    const float* bng      = (const float*)d_in[11];
    const float* bnb      = (const float*)d_in[12];
    float* out = (float*)d_out;
    int soft_n = out_size - 2;

    k_fused<<<dim3(256, 8), 256>>>(x_init, sample_w,
                                   ctx_w + 0*81, ctx_b + 0*3, bng + 0*3, bnb + 0*3);
    k_ctx1pool<<<2176, 256>>>(ctx_w + 1*81, ctx_b + 1*3, bng + 1*3, bnb + 1*3,
                              sample_w, sample_b,
                              pool1_w, pool1_b, pool2_w, pool2_b);
    k_tail23<<<512, 256>>>(ctx_w + 2*81, ctx_b + 2*3, bng + 2*3, bnb + 2*3,
                           ctx_w + 3*81, ctx_b + 3*3, bng + 3*3, bnb + 3*3);
    k_mega<<<3072, 256>>>(thresh, centers, sample_b, out, soft_n);
}

// round 9
// speedup vs baseline: 2.0237x; 1.0767x over previous
#include <cuda_runtime.h>
#include <math.h>

#define NB 8
#define NC 3

// ---------------- scratch (device globals; no runtime allocation) ----------------
__device__ float g_x [NB*NC*256*256];   // UNSCALED sample conv output (no sigma, no bias)
__device__ float g_h0[NB*NC*512*512];
__device__ float g_h1[NB*NC*256*256];
__device__ float g_h2[NB*NC*128*128];
__device__ float g_h3[NB*NC*64*64];
__device__ float g_p1[NB*NC*128*128];
__device__ float g_p2[NB*NC*64*64];
__device__ float g_inv_sigma;
__device__ unsigned int g_counts[8];    // zero-init at load; reset by mega finalize
__device__ unsigned int g_esti16;
__device__ unsigned int g_done = 0;
__device__ unsigned int g_bar_cnt = 0;
__device__ unsigned int g_bar_sense = 0;

// ---------------- fused: sample conv (4x4 s4, unscaled) + ctx stage 0 ----------------
__global__ void k_fused(const float* __restrict__ x,
                        const float* __restrict__ samw,
                        const float* __restrict__ cw,
                        const float* __restrict__ cb,
                        const float* __restrict__ bng,
                        const float* __restrict__ bnb) {
    __shared__ float ssw[144];
    __shared__ float scw[81], scb[3], sinv[3], sbb[3];
    int tid = threadIdx.x;
    if (tid < 144) ssw[tid] = samw[tid];
    if (tid < 81)  scw[tid] = cw[tid];
    if (tid < 3) {
        scb[tid]  = cb[tid];
        sinv[tid] = bng[tid] * rsqrtf(1.001f);
        sbb[tid]  = bnb[tid];
    }
    __syncthreads();

    int ox = threadIdx.x;
    int oy = blockIdx.x;
    int b  = blockIdx.y;

    float as0 = 0.f, as1 = 0.f, as2 = 0.f;
    float ac[2][2][3];
    #pragma unroll
    for (int sy = 0; sy < 2; sy++)
        #pragma unroll
        for (int sx = 0; sx < 2; sx++)
            #pragma unroll
            for (int oc = 0; oc < 3; oc++)
                ac[sy][sx][oc] = scb[oc];

    bool left = (ox > 0);

    #pragma unroll
    for (int ic = 0; ic < 3; ic++) {
        const float* base = x + (size_t)(b*3 + ic)*1024*1024;
        float inv = sinv[ic], bb = sbb[ic];
        #pragma unroll
        for (int r5 = 0; r5 < 5; r5++) {
            int iy = 4*oy + r5 - 1;
            float u0, u1, u2, u3, u4;
            if (iy >= 0) {
                const float* rp = base + (size_t)iy*1024 + 4*ox;
                float4 v4 = *reinterpret_cast<const float4*>(rp);
                float vm = left ? rp[-1] : 0.f;
                u0 = left ? fmaxf(fmaf(inv, vm, bb), 0.f) : 0.f;
                u1 = fmaxf(fmaf(inv, v4.x, bb), 0.f);
                u2 = fmaxf(fmaf(inv, v4.y, bb), 0.f);
                u3 = fmaxf(fmaf(inv, v4.z, bb), 0.f);
                u4 = fmaxf(fmaf(inv, v4.w, bb), 0.f);
                if (r5 >= 1) {
                    int ky = r5 - 1;
                    const float* w0 = &ssw[(0*3 + ic)*16 + ky*4];
                    const float* w1 = &ssw[(1*3 + ic)*16 + ky*4];
                    const float* w2 = &ssw[(2*3 + ic)*16 + ky*4];
                    as0 += w0[0]*v4.x + w0[1]*v4.y + w0[2]*v4.z + w0[3]*v4.w;
                    as1 += w1[0]*v4.x + w1[1]*v4.y + w1[2]*v4.z + w1[3]*v4.w;
                    as2 += w2[0]*v4.x + w2[1]*v4.y + w2[2]*v4.z + w2[3]*v4.w;
                }
            } else {
                u0 = u1 = u2 = u3 = u4 = 0.f;
            }
            if (r5 <= 2) {
                #pragma unroll
                for (int oc = 0; oc < 3; oc++) {
                    const float* wp = &scw[oc*27 + ic*9 + r5*3];
                    ac[0][0][oc] = fmaf(wp[0], u0, fmaf(wp[1], u1, fmaf(wp[2], u2, ac[0][0][oc])));
                    ac[0][1][oc] = fmaf(wp[0], u2, fmaf(wp[1], u3, fmaf(wp[2], u4, ac[0][1][oc])));
                }
            }
            if (r5 >= 2) {
                int ky = r5 - 2;
                #pragma unroll
                for (int oc = 0; oc < 3; oc++) {
                    const float* wp = &scw[oc*27 + ic*9 + ky*3];
                    ac[1][0][oc] = fmaf(wp[0], u0, fmaf(wp[1], u1, fmaf(wp[2], u2, ac[1][0][oc])));
                    ac[1][1][oc] = fmaf(wp[0], u2, fmaf(wp[1], u3, fmaf(wp[2], u4, ac[1][1][oc])));
                }
            }
        }
    }

    g_x[((b*3 + 0)*256 + oy)*256 + ox] = as0;
    g_x[((b*3 + 1)*256 + oy)*256 + ox] = as1;
    g_x[((b*3 + 2)*256 + oy)*256 + ox] = as2;

    #pragma unroll
    for (int oc = 0; oc < 3; oc++) {
        #pragma unroll
        for (int sy = 0; sy < 2; sy++) {
            size_t o = ((size_t)(b*3 + oc)*512 + 2*oy + sy)*512 + 2*ox;
            *reinterpret_cast<float2*>(g_h0 + o) = make_float2(ac[sy][0][oc], ac[sy][1][oc]);
        }
    }
}

// ---------------- per-pixel ctx conv body (stages 1..3) ----------------
template<int STAGE>
__device__ __forceinline__ void ctx_px_body(int i,
                                            const float* sw, const float* sb,
                                            const float* sinv, const float* sbb) {
    constexpr int INH  = (STAGE == 1) ? 512 : (STAGE == 2) ? 256 : 128;
    constexpr int OUTW = INH / 2;
    constexpr int LOG  = (STAGE == 1) ? 8 : (STAGE == 2) ? 7 : 6;
    const float* in = (STAGE == 1) ? g_h0 : (STAGE == 2) ? g_h1 : g_h2;
    float* outp     = (STAGE == 1) ? g_h1 : (STAGE == 2) ? g_h2 : g_h3;

    int ox = i & (OUTW - 1);
    int oy = (i >> LOG) & (OUTW - 1);
    int b  = i >> (2*LOG);

    float a0 = sb[0], a1 = sb[1], a2 = sb[2];
    bool left = (ox > 0);
    #pragma unroll
    for (int ic = 0; ic < 3; ic++) {
        const float* base = in + (size_t)(b*3 + ic)*INH*INH;
        float inv = sinv[ic], bb = sbb[ic];
        #pragma unroll
        for (int r = 0; r < 3; r++) {
            int iy = 2*oy + r - 1;
            float uL = 0.f, u0 = 0.f, u1 = 0.f;
            if (iy >= 0) {
                const float* rp = base + (size_t)iy*INH + 2*ox;
                float2 v = *reinterpret_cast<const float2*>(rp);
                u0 = fmaxf(fmaf(inv, v.x, bb), 0.f);
                u1 = fmaxf(fmaf(inv, v.y, bb), 0.f);
                if (left) uL = fmaxf(fmaf(inv, rp[-1], bb), 0.f);
            }
            const float* wp = &sw[ic*9 + r*3];
            a0 = fmaf(wp[0],  uL, fmaf(wp[1],  u0, fmaf(wp[2],  u1, a0)));
            a1 = fmaf(wp[27], uL, fmaf(wp[28], u0, fmaf(wp[29], u1, a1)));
            a2 = fmaf(wp[54], uL, fmaf(wp[55], u0, fmaf(wp[56], u1, a2)));
        }
    }
    outp[((b*3 + 0)*OUTW + oy)*OUTW + ox] = a0;
    outp[((b*3 + 1)*OUTW + oy)*OUTW + ox] = a1;
    outp[((b*3 + 2)*OUTW + oy)*OUTW + ox] = a2;
}

// ---------------- role-split: ctx1 (blocks [0,2048)) + pools (blocks [2048,2176)) ----------------
__global__ void k_ctx1pool(const float* __restrict__ w1c, const float* __restrict__ b1c,
                           const float* __restrict__ bng1, const float* __restrict__ bnb1,
                           const float* __restrict__ samw, const float* __restrict__ samb,
                           const float* __restrict__ pw1, const float* __restrict__ pb1,
                           const float* __restrict__ pw2, const float* __restrict__ pb2) {
    int tid = threadIdx.x;
    if (blockIdx.x < 2048) {
        __shared__ float sw[81], sb[3], sinv[3], sbb[3];
        for (int t = tid; t < 81; t += 256) sw[t] = w1c[t];
        if (tid < 3) {
            sb[tid]   = b1c[tid];
            sinv[tid] = bng1[tid] * rsqrtf(1.001f);
            sbb[tid]  = bnb1[tid];
        }
        __syncthreads();
        int i = blockIdx.x*256 + tid;
        ctx_px_body<1>(i, sw, sb, sinv, sbb);
    } else {
        __shared__ float sG[9];
        __shared__ float sis;
        __shared__ float sw1[36], sw2[36], sb1[3], sb2[3], sbs[3];
        if (tid < 36) { sw1[tid] = pw1[tid]; sw2[tid] = pw2[tid]; }
        if (tid >= 64 && tid < 67) {
            int c = tid - 64;
            sb1[c] = pb1[c]; sb2[c] = pb2[c]; sbs[c] = samb[c];
        }
        if (tid >= 96 && tid < 105) {
            int t9 = tid - 96;
            int ii = t9 / 3, jj = t9 % 3;
            float s0 = 0.f, s1 = 0.f, s2 = 0.f, s3 = 0.f;
            #pragma unroll
            for (int k = 0; k < 48; k += 4) {
                s0 += samw[ii*48 + k + 0] * samw[jj*48 + k + 0];
                s1 += samw[ii*48 + k + 1] * samw[jj*48 + k + 1];
                s2 += samw[ii*48 + k + 2] * samw[jj*48 + k + 2];
                s3 += samw[ii*48 + k + 3] * samw[jj*48 + k + 3];
            }
            sG[t9] = (s0 + s1) + (s2 + s3);
        }
        __syncthreads();
        if (tid == 0) {
            float g00 = sG[0], g01 = sG[1], g02 = sG[2];
            float g11 = sG[4], g12 = sG[5], g22 = sG[8];
            float q  = (g00 + g11 + g22) * (1.f/3.f);
            float pp = g01*g01 + g02*g02 + g12*g12;
            float d0 = g00 - q, d1 = g11 - q, d2 = g22 - q;
            float p2 = d0*d0 + d1*d1 + d2*d2 + 2.f*pp;
            float lam;
            if (p2 <= 1e-30f) {
                lam = q;
            } else {
                float p  = sqrtf(p2 * (1.f/6.f));
                float ip = 1.f/p;
                float b00 = d0*ip, b11 = d1*ip, b22 = d2*ip;
                float b01 = g01*ip, b02 = g02*ip, b12 = g12*ip;
                float detB = b00*(b11*b22 - b12*b12)
                           - b01*(b01*b22 - b12*b02)
                           + b02*(b01*b12 - b11*b02);
                float r = fminf(1.f, fmaxf(-1.f, 0.5f*detB));
                lam = q + 2.f*p*cosf(acosf(r)*(1.f/3.f));
            }
            float is = rsqrtf(lam);
            sis = is;
            if (blockIdx.x == 2048) g_inv_sigma = is;
        }
        __syncthreads();
        float is = sis;

        int i  = (blockIdx.x - 2048)*256 + tid;
        int ox = i & 63;
        int oy = (i >> 6) & 63;
        int b  = i >> 12;

        float p1v[2][2][3];
        #pragma unroll
        for (int sy = 0; sy < 2; sy++)
            #pragma unroll
            for (int sx = 0; sx < 2; sx++)
                #pragma unroll
                for (int mc = 0; mc < 3; mc++)
                    p1v[sy][sx][mc] = sb1[mc];

        #pragma unroll
        for (int ic = 0; ic < 3; ic++) {
            const float* base = g_x + (size_t)(b*3 + ic)*65536 + (size_t)(4*oy)*256 + 4*ox;
            float bsc = sbs[ic];
            float rx[4][4];
            #pragma unroll
            for (int r = 0; r < 4; r++) {
                float4 v = *reinterpret_cast<const float4*>(base + r*256);
                rx[r][0] = fmaf(v.x, is, bsc);
                rx[r][1] = fmaf(v.y, is, bsc);
                rx[r][2] = fmaf(v.z, is, bsc);
                rx[r][3] = fmaf(v.w, is, bsc);
            }
            #pragma unroll
            for (int mc = 0; mc < 3; mc++) {
                const float* wp = &sw1[mc*12 + ic*4];
                #pragma unroll
                for (int sy = 0; sy < 2; sy++)
                    #pragma unroll
                    for (int sx = 0; sx < 2; sx++)
                        p1v[sy][sx][mc] += wp[0]*rx[2*sy][2*sx]   + wp[1]*rx[2*sy][2*sx+1]
                                         + wp[2]*rx[2*sy+1][2*sx] + wp[3]*rx[2*sy+1][2*sx+1];
            }
        }

        #pragma unroll
        for (int mc = 0; mc < 3; mc++)
            #pragma unroll
            for (int sy = 0; sy < 2; sy++) {
                size_t o = ((size_t)(b*3 + mc)*128 + 2*oy + sy)*128 + 2*ox;
                *reinterpret_cast<float2*>(g_p1 + o) = make_float2(p1v[sy][0][mc], p1v[sy][1][mc]);
            }

        #pragma unroll
        for (int oc = 0; oc < 3; oc++) {
            float a = sb2[oc];
            #pragma unroll
            for (int mc = 0; mc < 3; mc++) {
                const float* wp = &sw2[oc*12 + mc*4];
                a += wp[0]*p1v[0][0][mc] + wp[1]*p1v[0][1][mc]
                   + wp[2]*p1v[1][0][mc] + wp[3]*p1v[1][1][mc];
            }
            g_p2[((size_t)(b*3 + oc)*64 + oy)*64 + ox] = a;
        }
    }
}

// ---------------- ctx2 + ctx3 in one kernel with a co-resident grid barrier ----------------
__global__ void __launch_bounds__(256, 4)
k_tail23(const float* __restrict__ w2c, const float* __restrict__ b2c,
         const float* __restrict__ bng2, const float* __restrict__ bnb2,
         const float* __restrict__ w3c, const float* __restrict__ b3c,
         const float* __restrict__ bng3, const float* __restrict__ bnb3) {
    __shared__ float sw2[81], sb2[3], sinv2[3], sbb2[3];
    __shared__ float sw3[81], sb3[3], sinv3[3], sbb3[3];
    int tid = threadIdx.x;
    for (int t = tid; t < 81; t += 256) { sw2[t] = w2c[t]; sw3[t] = w3c[t]; }
    if (tid < 3) {
        sb2[tid]   = b2c[tid];
        sinv2[tid] = bng2[tid] * rsqrtf(1.001f);
        sbb2[tid]  = bnb2[tid];
        sb3[tid]   = b3c[tid];
        sinv3[tid] = bng3[tid] * rsqrtf(1.001f);
        sbb3[tid]  = bnb3[tid];
    }
    __syncthreads();

    int i = blockIdx.x*256 + tid;
    ctx_px_body<2>(i, sw2, sb2, sinv2, sbb2);

    __threadfence();
    __syncthreads();
    if (tid == 0) {
        unsigned int S = *(volatile unsigned int*)&g_bar_sense;
        unsigned int a = atomicAdd(&g_bar_cnt, 1u);
        if (a == gridDim.x - 1u) {
            g_bar_cnt = 0u;
            __threadfence();
            atomicExch(&g_bar_sense, S ^ 1u);
        } else {
            while (*(volatile unsigned int*)&g_bar_sense == S) { }
        }
    }
    __syncthreads();

    if (i < NB*64*64) {
        ctx_px_body<3>(i, sw3, sb3, sinv3, sbb3);
    }
}

// ---------------- soft VQ of one scalar + histogram count ----------------
__device__ __forceinline__ float vq8(float x, const float* sc, unsigned int* shist) {
    float dd[8];
    float dmin = 3.4e38f;
    int imin = 0;
    #pragma unroll
    for (int k = 0; k < 8; k++) {
        float d = (x - sc[k])*(x - sc[k]);
        dd[k] = d;
        if (d < dmin) { dmin = d; imin = k; }
    }
    float s = 0.f, sn = 0.f;
    #pragma unroll
    for (int k = 0; k < 8; k++) {
        float e = __expf(dmin - dd[k]);
        s += e;
        sn = fmaf(e, sc[k], sn);
    }
    atomicAdd(&shist[imin], 1u);
    return __fdividef(sn, s);
}

// ---------------- mega: one thread per quarter-res cell -> 4x4 pixel block ----------------
// Conditions are constant within each half-res cell; xq is shared within the cell
// for c1 (p1 value) and within the quarter cell for c2 (p2 value). mask_1 == c1
// per half-cell, mask_2 == c2 per quarter cell, so all three histograms collapse
// into this single walk. esti in 1/16 units: c2 cell=16, c1 half=16, c0 half=64.
__global__ void k_mega(const float* __restrict__ thresh,
                       const float* __restrict__ centers,
                       const float* __restrict__ samb,
                       float* __restrict__ out, int soft_n) {
    __shared__ float sc[8];
    __shared__ unsigned int shist[8];
    __shared__ unsigned int sesti;
    __shared__ float sth[2];
    __shared__ float sbs[3];
    __shared__ float s_is;
    int tid = threadIdx.x;
    if (tid < 8) { sc[tid] = centers[tid]; shist[tid] = 0u; }
    if (tid < 2) sth[tid] = thresh[tid];
    if (tid < 3) sbs[tid] = samb[tid];
    if (tid == 0) { sesti = 0u; s_is = g_inv_sigma; }
    __syncthreads();

    int t = blockIdx.x*256 + tid;           // quarter cell index, 0..98303 (grid exact)
    int qx = t & 63, qy = (t >> 6) & 63, bc = t >> 12;
    int pbase = bc*65536 + (qy*4)*256 + qx*4;

    unsigned int units;
    float f2 = 0.5f*(tanhf(g_h3[t]) + 1.0f);
    if (f2 < sth[1]) {
        // c2: whole 4x4 block shares xq = p2[qi]
        float v = vq8(g_p2[t], sc, shist);
        units = 16u;
        float4 vv = make_float4(v, v, v, v);
        #pragma unroll
        for (int r = 0; r < 4; r++)
            *reinterpret_cast<float4*>(out + pbase + r*256) = vv;
    } else {
        units = 0u;
        float is = s_is;
        float bsc = sbs[bc % 3];
        #pragma unroll
        for (int hy = 0; hy < 2; hy++) {
            #pragma unroll
            for (int hx = 0; hx < 2; hx++) {
                int hi = bc*16384 + (qy*2 + hy)*128 + (qx*2 + hx);
                int hb = pbase + hy*2*256 + hx*2;
                float f1 = 0.5f*(tanhf(g_h2[hi]) + 1.0f);
                if (f1 < sth[0]) {
                    // c1: 2x2 sub-block shares xq = p1[hi]
                    float v = vq8(g_p1[hi], sc, shist);
                    units += 16u;
                    float2 vv = make_float2(v, v);
                    *reinterpret_cast<float2*>(out + hb)       = vv;
                    *reinterpret_cast<float2*>(out + hb + 256) = vv;
                } else {
                    // c0: per-pixel soft VQ on x
                    units += 64u;
                    #pragma unroll
                    for (int r = 0; r < 2; r++) {
                        float2 xv = *reinterpret_cast<const float2*>(g_x + hb + r*256);
                        float x0 = fmaf(xv.x, is, bsc);
                        float x1 = fmaf(xv.y, is, bsc);
                        float v0 = vq8(x0, sc, shist);
                        float v1 = vq8(x1, sc, shist);
                        *reinterpret_cast<float2*>(out + hb + r*256) = make_float2(v0, v1);
                    }
                }
            }
        }
    }

    unsigned int wsum = __reduce_add_sync(0xffffffffu, units);
    if ((tid & 31) == 0) atomicAdd(&sesti, wsum);
    __syncthreads();
    if (tid < 8) {
        if (shist[tid]) atomicAdd(&g_counts[tid], shist[tid]);
        if (tid == 0) atomicAdd(&g_esti16, sesti);
        __threadfence();
    }
    __syncthreads();

    if (tid == 0) {
        unsigned int ticket = atomicAdd(&g_done, 1u);
        if (ticket == gridDim.x - 1) {
            double tot = 0.0;
            double c[8];
            for (int k = 0; k < 8; k++) {
                c[k] = (double)atomicAdd(&g_counts[k], 0u);
                tot += c[k];
            }
            double mean = 0.0;
            for (int k = 0; k < 8; k++) { c[k] /= tot; mean += c[k]; }
            mean /= 8.0;
            double var = 0.0;
            for (int k = 0; k < 8; k++) { double d = c[k] - mean; var += d*d; }
            double stdv = sqrt(var / 7.0);
            double esti = (double)atomicAdd(&g_esti16, 0u) / 16.0;
            double cr = (1.0/16.0) * esti / (256.0*256.0*3.0*8.0);
            out[soft_n]     = (float)cr;
            out[soft_n + 1] = (float)stdv;
            for (int k = 0; k < 8; k++) g_counts[k] = 0u;
            g_esti16 = 0u;
            __threadfence();
            atomicExch(&g_done, 0u);
        }
    }
}

// ---------------- launch ----------------
extern "C" void kernel_launch(void* const* d_in, const int* in_sizes, int n_in,
                              void* d_out, int out_size) {
    const float* x_init   = (const float*)d_in[0];
    const float* thresh   = (const float*)d_in[1];
    const float* sample_w = (const float*)d_in[2];
    const float* sample_b = (const float*)d_in[3];
    const float* centers  = (const float*)d_in[4];
    const float* pool1_w  = (const float*)d_in[5];
    const float* pool1_b  = (const float*)d_in[6];
    const float* pool2_w  = (const float*)d_in[7];
    const float* pool2_b  = (const float*)d_in[8];
    const float* ctx_w    = (const float*)d_in[9];
    const float* ctx_b    = (const float*)d_in[10];
    const float* bng      = (const float*)d_in[11];
    const float* bnb      = (const float*)d_in[12];
    float* out = (float*)d_out;
    int soft_n = out_size - 2;

    k_fused<<<dim3(256, 8), 256>>>(x_init, sample_w,
                                   ctx_w + 0*81, ctx_b + 0*3, bng + 0*3, bnb + 0*3);
    k_ctx1pool<<<2176, 256>>>(ctx_w + 1*81, ctx_b + 1*3, bng + 1*3, bnb + 1*3,
                              sample_w, sample_b,
                              pool1_w, pool1_b, pool2_w, pool2_b);
    k_tail23<<<512, 256>>>(ctx_w + 2*81, ctx_b + 2*3, bng + 2*3, bnb + 2*3,
                           ctx_w + 3*81, ctx_b + 3*3, bng + 3*3, bnb + 3*3);
    k_mega<<<384, 256>>>(thresh, centers, sample_b, out, soft_n);
}